// round 1
// baseline (speedup 1.0000x reference)
#include <cuda_runtime.h>
#include <cuda_bf16.h>
#include <math_constants.h>

// Problem constants
#define NN   12288
#define DIM  128
#define HID  16
#define CLS  16

// Aggregation tiling
#define BM        512   // rows per block (256 threads x 2 rows/thread)
#define NSPLIT    12    // column splits (grid.y)
#define COLS_PS   (NN / NSPLIT)   // 1024 columns per split
#define CHUNK     256   // columns staged in smem per pass

// Device scratch (no cudaMalloc allowed)
__device__ __align__(16) float g_H[NN * HID];                    // hidden features [N,16]
__device__ __align__(16) float g_pnum[NSPLIT * NN * CLS];        // partial numerators
__device__ __align__(16) float g_pden[NSPLIT * NN];              // partial denominators

// ---------------------------------------------------------------------------
// Kernel 1: h = ((x@W1+b1)@W2+b2)@W3+b3  -> g_H
// One thread per row. Weights staged in shared memory (broadcast reads).
// ---------------------------------------------------------------------------
__global__ void mlp_kernel(const float* __restrict__ x,
                           const float* __restrict__ W1, const float* __restrict__ b1,
                           const float* __restrict__ W2, const float* __restrict__ b2,
                           const float* __restrict__ W3, const float* __restrict__ b3) {
    __shared__ float sW1[DIM * HID];
    __shared__ float sW2[HID * HID];
    __shared__ float sW3[HID * CLS];
    __shared__ float sb1[HID], sb2[HID], sb3[CLS];

    const int tid = threadIdx.x;
    for (int i = tid; i < DIM * HID; i += blockDim.x) sW1[i] = W1[i];
    for (int i = tid; i < HID * HID; i += blockDim.x) sW2[i] = W2[i];
    for (int i = tid; i < HID * CLS; i += blockDim.x) sW3[i] = W3[i];
    if (tid < HID) { sb1[tid] = b1[tid]; sb2[tid] = b2[tid]; }
    if (tid < CLS) { sb3[tid] = b3[tid]; }
    __syncthreads();

    const int row = blockIdx.x * blockDim.x + tid;
    if (row >= NN) return;

    float h1[HID];
#pragma unroll
    for (int j = 0; j < HID; j++) h1[j] = sb1[j];

    const float4* xr = reinterpret_cast<const float4*>(x + (size_t)row * DIM);
#pragma unroll 4
    for (int k4 = 0; k4 < DIM / 4; k4++) {
        float4 xv = __ldg(&xr[k4]);
        const int k = k4 * 4;
#pragma unroll
        for (int j = 0; j < HID; j++) {
            h1[j] = fmaf(xv.x, sW1[(k + 0) * HID + j], h1[j]);
            h1[j] = fmaf(xv.y, sW1[(k + 1) * HID + j], h1[j]);
            h1[j] = fmaf(xv.z, sW1[(k + 2) * HID + j], h1[j]);
            h1[j] = fmaf(xv.w, sW1[(k + 3) * HID + j], h1[j]);
        }
    }

    float h2[HID];
#pragma unroll
    for (int j = 0; j < HID; j++) h2[j] = sb2[j];
#pragma unroll
    for (int k = 0; k < HID; k++) {
#pragma unroll
        for (int j = 0; j < HID; j++) h2[j] = fmaf(h1[k], sW2[k * HID + j], h2[j]);
    }

    float h3[CLS];
#pragma unroll
    for (int j = 0; j < CLS; j++) h3[j] = sb3[j];
#pragma unroll
    for (int k = 0; k < HID; k++) {
#pragma unroll
        for (int j = 0; j < CLS; j++) h3[j] = fmaf(h2[k], sW3[k * CLS + j], h3[j]);
    }

    float4* dst = reinterpret_cast<float4*>(g_H + (size_t)row * CLS);
    dst[0] = make_float4(h3[0],  h3[1],  h3[2],  h3[3]);
    dst[1] = make_float4(h3[4],  h3[5],  h3[6],  h3[7]);
    dst[2] = make_float4(h3[8],  h3[9],  h3[10], h3[11]);
    dst[3] = make_float4(h3[12], h3[13], h3[14], h3[15]);
}

// ---------------------------------------------------------------------------
// Kernel 2: fused masked-softmax aggregation (flash-style, no max needed).
// For rows r owned by this block and columns of this split:
//   s = h_r . h_j ;  e = (s > 0) ? exp(s) : 0
//   num[r,:] += e * h_j[:] ;  den[r] += e
// Partials written per column-split; reduced in kernel 3.
// ---------------------------------------------------------------------------
__device__ __forceinline__ float dot16(const float* hi, float4 a, float4 b, float4 c, float4 d) {
    float q0 = hi[0] * a.x;  q0 = fmaf(hi[1],  a.y, q0); q0 = fmaf(hi[2],  a.z, q0); q0 = fmaf(hi[3],  a.w, q0);
    float q1 = hi[4] * b.x;  q1 = fmaf(hi[5],  b.y, q1); q1 = fmaf(hi[6],  b.z, q1); q1 = fmaf(hi[7],  b.w, q1);
    float q2 = hi[8] * c.x;  q2 = fmaf(hi[9],  c.y, q2); q2 = fmaf(hi[10], c.z, q2); q2 = fmaf(hi[11], c.w, q2);
    float q3 = hi[12] * d.x; q3 = fmaf(hi[13], d.y, q3); q3 = fmaf(hi[14], d.z, q3); q3 = fmaf(hi[15], d.w, q3);
    return (q0 + q1) + (q2 + q3);
}

__global__ __launch_bounds__(256, 2)
void agg_kernel() {
    const int tid = threadIdx.x;
    const int r0 = blockIdx.x * BM + tid;
    const int r1 = r0 + 256;

    const float4* H4 = reinterpret_cast<const float4*>(g_H);

    float hi0[16], hi1[16];
#pragma unroll
    for (int q = 0; q < 4; q++) {
        float4 t0 = H4[r0 * 4 + q];
        hi0[q * 4 + 0] = t0.x; hi0[q * 4 + 1] = t0.y; hi0[q * 4 + 2] = t0.z; hi0[q * 4 + 3] = t0.w;
        float4 t1 = H4[r1 * 4 + q];
        hi1[q * 4 + 0] = t1.x; hi1[q * 4 + 1] = t1.y; hi1[q * 4 + 2] = t1.z; hi1[q * 4 + 3] = t1.w;
    }

    float num0[16], num1[16];
#pragma unroll
    for (int c = 0; c < 16; c++) { num0[c] = 0.f; num1[c] = 0.f; }
    float den0 = 0.f, den1 = 0.f;

    __shared__ float4 sh[CHUNK * 4];   // 16 KB: CHUNK columns x 16 floats

    const int c0 = blockIdx.y * COLS_PS;
    for (int cc = 0; cc < COLS_PS; cc += CHUNK) {
        __syncthreads();
        const float4* src = H4 + (size_t)(c0 + cc) * 4;
#pragma unroll
        for (int i = 0; i < 4; i++) sh[tid + i * 256] = src[tid + i * 256];
        __syncthreads();

        for (int j = 0; j < CHUNK; j++) {
            const float4 a = sh[j * 4 + 0];
            const float4 b = sh[j * 4 + 1];
            const float4 c = sh[j * 4 + 2];
            const float4 d = sh[j * 4 + 3];

            const float s0 = dot16(hi0, a, b, c, d);
            const float s1 = dot16(hi1, a, b, c, d);
            float e0 = __expf(s0); e0 = (s0 > 0.f) ? e0 : 0.f;
            float e1 = __expf(s1); e1 = (s1 > 0.f) ? e1 : 0.f;
            den0 += e0; den1 += e1;

            num0[0]  = fmaf(e0, a.x, num0[0]);  num1[0]  = fmaf(e1, a.x, num1[0]);
            num0[1]  = fmaf(e0, a.y, num0[1]);  num1[1]  = fmaf(e1, a.y, num1[1]);
            num0[2]  = fmaf(e0, a.z, num0[2]);  num1[2]  = fmaf(e1, a.z, num1[2]);
            num0[3]  = fmaf(e0, a.w, num0[3]);  num1[3]  = fmaf(e1, a.w, num1[3]);
            num0[4]  = fmaf(e0, b.x, num0[4]);  num1[4]  = fmaf(e1, b.x, num1[4]);
            num0[5]  = fmaf(e0, b.y, num0[5]);  num1[5]  = fmaf(e1, b.y, num1[5]);
            num0[6]  = fmaf(e0, b.z, num0[6]);  num1[6]  = fmaf(e1, b.z, num1[6]);
            num0[7]  = fmaf(e0, b.w, num0[7]);  num1[7]  = fmaf(e1, b.w, num1[7]);
            num0[8]  = fmaf(e0, c.x, num0[8]);  num1[8]  = fmaf(e1, c.x, num1[8]);
            num0[9]  = fmaf(e0, c.y, num0[9]);  num1[9]  = fmaf(e1, c.y, num1[9]);
            num0[10] = fmaf(e0, c.z, num0[10]); num1[10] = fmaf(e1, c.z, num1[10]);
            num0[11] = fmaf(e0, c.w, num0[11]); num1[11] = fmaf(e1, c.w, num1[11]);
            num0[12] = fmaf(e0, d.x, num0[12]); num1[12] = fmaf(e1, d.x, num1[12]);
            num0[13] = fmaf(e0, d.y, num0[13]); num1[13] = fmaf(e1, d.y, num1[13]);
            num0[14] = fmaf(e0, d.z, num0[14]); num1[14] = fmaf(e1, d.z, num1[14]);
            num0[15] = fmaf(e0, d.w, num0[15]); num1[15] = fmaf(e1, d.w, num1[15]);
        }
    }

    const int s = blockIdx.y;
    float4* pn = reinterpret_cast<float4*>(g_pnum + (size_t)s * NN * CLS);
#pragma unroll
    for (int q = 0; q < 4; q++) {
        pn[r0 * 4 + q] = make_float4(num0[q * 4 + 0], num0[q * 4 + 1], num0[q * 4 + 2], num0[q * 4 + 3]);
        pn[r1 * 4 + q] = make_float4(num1[q * 4 + 0], num1[q * 4 + 1], num1[q * 4 + 2], num1[q * 4 + 3]);
    }
    g_pden[s * NN + r0] = den0;
    g_pden[s * NN + r1] = den1;
}

// ---------------------------------------------------------------------------
// Kernel 3: reduce split partials, out = num/den, then row log-softmax.
// ---------------------------------------------------------------------------
__global__ void finalize_kernel(float* __restrict__ out) {
    const int row = blockIdx.x * blockDim.x + threadIdx.x;
    if (row >= NN) return;

    float acc[16];
#pragma unroll
    for (int c = 0; c < 16; c++) acc[c] = 0.f;
    float den = 0.f;

#pragma unroll
    for (int s = 0; s < NSPLIT; s++) {
        const float4* pn = reinterpret_cast<const float4*>(g_pnum + (size_t)s * NN * CLS + (size_t)row * CLS);
#pragma unroll
        for (int q = 0; q < 4; q++) {
            float4 v = pn[q];
            acc[q * 4 + 0] += v.x; acc[q * 4 + 1] += v.y;
            acc[q * 4 + 2] += v.z; acc[q * 4 + 3] += v.w;
        }
        den += g_pden[s * NN + row];
    }

    const float inv = 1.0f / den;
    float o[16];
    float m = -CUDART_INF_F;
#pragma unroll
    for (int c = 0; c < 16; c++) { o[c] = acc[c] * inv; m = fmaxf(m, o[c]); }
    float sum = 0.f;
#pragma unroll
    for (int c = 0; c < 16; c++) sum += expf(o[c] - m);
    const float lse = logf(sum) + m;

    float4* dst = reinterpret_cast<float4*>(out + (size_t)row * CLS);
#pragma unroll
    for (int q = 0; q < 4; q++) {
        dst[q] = make_float4(o[q * 4 + 0] - lse, o[q * 4 + 1] - lse,
                             o[q * 4 + 2] - lse, o[q * 4 + 3] - lse);
    }
}

// ---------------------------------------------------------------------------
extern "C" void kernel_launch(void* const* d_in, const int* in_sizes, int n_in,
                              void* d_out, int out_size) {
    const float* x  = (const float*)d_in[0];
    const float* W1 = (const float*)d_in[1];
    const float* b1 = (const float*)d_in[2];
    const float* W2 = (const float*)d_in[3];
    const float* b2 = (const float*)d_in[4];
    const float* W3 = (const float*)d_in[5];
    const float* b3 = (const float*)d_in[6];
    float* out = (float*)d_out;

    mlp_kernel<<<NN / 128, 128>>>(x, W1, b1, W2, b2, W3, b3);

    dim3 grid(NN / BM, NSPLIT);
    agg_kernel<<<grid, 256>>>();

    finalize_kernel<<<NN / 256, 256>>>(out);
}

// round 2
// speedup vs baseline: 2.6369x; 2.6369x over previous
#include <cuda_runtime.h>
#include <cuda_bf16.h>
#include <math_constants.h>
#include <cstdint>

// Problem constants
#define NN   12288
#define DIM  128
#define HID  16
#define CLS  16

// Aggregation tiling
#define NSPLIT   3
#define COLS_PS  (NN / NSPLIT)     // 4096 columns per split
#define CHUNK    128               // columns staged per pass
#define ROWS_CTA 128               // 8 warps x 16 rows

// smem strides (bf16 elements) chosen for conflict-free LDS.32 patterns
#define S_N 24     // natural layout Hc[j][hid], j-stride
#define S_T 136    // transposed layout HcT[hid][j], hid-stride

// Device scratch (no cudaMalloc allowed)
__device__ __align__(16) __nv_bfloat16 g_Hb[NN * HID];        // hidden features bf16
__device__ __align__(16) float g_pnum[NSPLIT * NN * CLS];     // partial numerators
__device__ __align__(16) float g_pden[NSPLIT * NN];           // partial denominators

// ---------------------------------------------------------------------------
// PTX helpers
// ---------------------------------------------------------------------------
__device__ __forceinline__ void mma_bf16(float& d0, float& d1, float& d2, float& d3,
                                         uint32_t a0, uint32_t a1, uint32_t a2, uint32_t a3,
                                         uint32_t b0, uint32_t b1) {
    asm volatile(
        "mma.sync.aligned.m16n8k16.row.col.f32.bf16.bf16.f32 "
        "{%0,%1,%2,%3}, {%4,%5,%6,%7}, {%8,%9}, {%0,%1,%2,%3};"
        : "+f"(d0), "+f"(d1), "+f"(d2), "+f"(d3)
        : "r"(a0), "r"(a1), "r"(a2), "r"(a3), "r"(b0), "r"(b1));
}

// packs {lo, hi} -> bf16x2 register (lo in low 16 bits)
__device__ __forceinline__ uint32_t cvt_bf16x2(float lo, float hi) {
    uint32_t r;
    asm("cvt.rn.bf16x2.f32 %0, %1, %2;" : "=r"(r) : "f"(hi), "f"(lo));
    return r;
}

// ---------------------------------------------------------------------------
// Kernel 1: h = ((x@W1+b1)@W2+b2)@W3+b3 -> g_Hb (bf16)
// 4 threads cooperate per row on the 128-dim layer-1 reduction.
// ---------------------------------------------------------------------------
__global__ __launch_bounds__(256)
void mlp_kernel(const float* __restrict__ x,
                const float* __restrict__ W1, const float* __restrict__ b1,
                const float* __restrict__ W2, const float* __restrict__ b2,
                const float* __restrict__ W3, const float* __restrict__ b3) {
    __shared__ float sW1[DIM * HID];
    __shared__ float sW2[HID * HID];
    __shared__ float sW3[HID * CLS];
    __shared__ float sb1[HID], sb2[HID], sb3[CLS];

    const int tid = threadIdx.x;
    for (int i = tid; i < DIM * HID; i += 256) sW1[i] = W1[i];
    for (int i = tid; i < HID * HID; i += 256) sW2[i] = W2[i];
    for (int i = tid; i < HID * CLS; i += 256) sW3[i] = W3[i];
    if (tid < HID) { sb1[tid] = b1[tid]; sb2[tid] = b2[tid]; }
    if (tid < CLS) { sb3[tid] = b3[tid]; }
    __syncthreads();

    const int sub = tid & 3;                       // 4 threads per row
    const int row = blockIdx.x * 64 + (tid >> 2);

    float p[HID];
#pragma unroll
    for (int j = 0; j < HID; j++) p[j] = 0.f;

    const float4* xr = reinterpret_cast<const float4*>(x + (size_t)row * DIM + sub * 32);
#pragma unroll
    for (int k4 = 0; k4 < 8; k4++) {
        float4 xv = __ldg(&xr[k4]);
        const int k = sub * 32 + k4 * 4;
#pragma unroll
        for (int j = 0; j < HID; j++) {
            p[j] = fmaf(xv.x, sW1[(k + 0) * HID + j], p[j]);
            p[j] = fmaf(xv.y, sW1[(k + 1) * HID + j], p[j]);
            p[j] = fmaf(xv.z, sW1[(k + 2) * HID + j], p[j]);
            p[j] = fmaf(xv.w, sW1[(k + 3) * HID + j], p[j]);
        }
    }

    float h1[HID];
#pragma unroll
    for (int j = 0; j < HID; j++) {
        float v = p[j];
        v += __shfl_xor_sync(0xffffffffu, v, 1);
        v += __shfl_xor_sync(0xffffffffu, v, 2);
        h1[j] = v + sb1[j];
    }

    float h2[HID];
#pragma unroll
    for (int j = 0; j < HID; j++) h2[j] = sb2[j];
#pragma unroll
    for (int k = 0; k < HID; k++)
#pragma unroll
        for (int j = 0; j < HID; j++) h2[j] = fmaf(h1[k], sW2[k * HID + j], h2[j]);

    float h3[CLS];
#pragma unroll
    for (int j = 0; j < CLS; j++) h3[j] = sb3[j];
#pragma unroll
    for (int k = 0; k < HID; k++)
#pragma unroll
        for (int j = 0; j < CLS; j++) h3[j] = fmaf(h2[k], sW3[k * CLS + j], h3[j]);

    if (sub == 0) {
        uint32_t* dst = reinterpret_cast<uint32_t*>(g_Hb + (size_t)row * HID);
#pragma unroll
        for (int q = 0; q < 8; q++) dst[q] = cvt_bf16x2(h3[2 * q], h3[2 * q + 1]);
    }
}

// ---------------------------------------------------------------------------
// Kernel 2: fused masked-softmax aggregation on tensor cores.
// S = Hr @ Hc^T via m16n8k16 bf16 HMMA (fp32 accum), e = (s>0)?exp(s):0,
// O += P @ Hc via second HMMA reusing the C-fragment layout as A-fragment.
// Per-split partials go to g_pnum / g_pden.
// ---------------------------------------------------------------------------
__global__ __launch_bounds__(256)
void agg_kernel() {
    __shared__ __align__(16) __nv_bfloat16 sHn[CHUNK * S_N];  // Hc[j][hid]
    __shared__ __align__(16) __nv_bfloat16 sHt[HID * S_T];    // HcT[hid][j]

    const int tid  = threadIdx.x;
    const int lane = tid & 31;
    const int wid  = tid >> 5;        // 0..7
    const int g    = lane >> 2;       // 0..7
    const int t4   = lane & 3;        // 0..3

    const int split = blockIdx.y;
    const int rbase = blockIdx.x * ROWS_CTA + wid * 16;
    const int rg  = rbase + g;
    const int rg8 = rg + 8;

    // A-fragment (this warp's 16 rows of H, bf16), loop-invariant
    uint32_t a0 = *reinterpret_cast<const uint32_t*>(g_Hb + (size_t)rg  * HID + 2 * t4);
    uint32_t a1 = *reinterpret_cast<const uint32_t*>(g_Hb + (size_t)rg8 * HID + 2 * t4);
    uint32_t a2 = *reinterpret_cast<const uint32_t*>(g_Hb + (size_t)rg  * HID + 2 * t4 + 8);
    uint32_t a3 = *reinterpret_cast<const uint32_t*>(g_Hb + (size_t)rg8 * HID + 2 * t4 + 8);

    // O accumulators (16x16 per warp): n-tile 0 (hid 0..7), n-tile 1 (hid 8..15)
    float o00 = 0.f, o01 = 0.f, o02 = 0.f, o03 = 0.f;
    float o10 = 0.f, o11 = 0.f, o12 = 0.f, o13 = 0.f;
    float den_g = 0.f, den_g8 = 0.f;

    const int j0 = split * COLS_PS;

    for (int cc = 0; cc < COLS_PS; cc += CHUNK) {
        __syncthreads();
        // Stage CHUNK columns of H (bf16) into both layouts.
        // idx enumerates (j, hw): j = column, hw = which u32 (2 hid values).
#pragma unroll
        for (int it = 0; it < (CHUNK * 8) / 256; it++) {
            const int idx = tid + it * 256;
            const int j  = idx >> 3;
            const int hw = idx & 7;
            uint32_t v = *reinterpret_cast<const uint32_t*>(
                g_Hb + (size_t)(j0 + cc + j) * HID + hw * 2);
            *reinterpret_cast<uint32_t*>(&sHn[j * S_N + hw * 2]) = v;
            __nv_bfloat162 bp = *reinterpret_cast<__nv_bfloat162*>(&v);
            sHt[(2 * hw)     * S_T + j] = bp.x;
            sHt[(2 * hw + 1) * S_T + j] = bp.y;
        }
        __syncthreads();

#pragma unroll
        for (int kc = 0; kc < CHUNK / 16; kc++) {
            // ---- S-mma: two n8 tiles covering 16 columns j in [16kc, 16kc+16) ----
            const int ja = 16 * kc + g;
            const int jb = ja + 8;
            uint32_t b0a = *reinterpret_cast<const uint32_t*>(&sHn[ja * S_N + 2 * t4]);
            uint32_t b1a = *reinterpret_cast<const uint32_t*>(&sHn[ja * S_N + 2 * t4 + 8]);
            uint32_t b0b = *reinterpret_cast<const uint32_t*>(&sHn[jb * S_N + 2 * t4]);
            uint32_t b1b = *reinterpret_cast<const uint32_t*>(&sHn[jb * S_N + 2 * t4 + 8]);

            float s0 = 0.f, s1 = 0.f, s2 = 0.f, s3 = 0.f;
            float s4 = 0.f, s5 = 0.f, s6 = 0.f, s7 = 0.f;
            mma_bf16(s0, s1, s2, s3, a0, a1, a2, a3, b0a, b1a);
            mma_bf16(s4, s5, s6, s7, a0, a1, a2, a3, b0b, b1b);

            // ---- mask + exp ----
            float e0 = __expf(s0); e0 = (s0 > 0.f) ? e0 : 0.f;
            float e1 = __expf(s1); e1 = (s1 > 0.f) ? e1 : 0.f;
            float e2 = __expf(s2); e2 = (s2 > 0.f) ? e2 : 0.f;
            float e3 = __expf(s3); e3 = (s3 > 0.f) ? e3 : 0.f;
            float e4 = __expf(s4); e4 = (s4 > 0.f) ? e4 : 0.f;
            float e5 = __expf(s5); e5 = (s5 > 0.f) ? e5 : 0.f;
            float e6 = __expf(s6); e6 = (s6 > 0.f) ? e6 : 0.f;
            float e7 = __expf(s7); e7 = (s7 > 0.f) ? e7 : 0.f;

            den_g  += (e0 + e1) + (e4 + e5);
            den_g8 += (e2 + e3) + (e6 + e7);

            // ---- P (bf16) as A-fragment for the O-mma ----
            uint32_t pa0 = cvt_bf16x2(e0, e1);   // P[g][16kc+2t4 .. +1]
            uint32_t pa1 = cvt_bf16x2(e2, e3);   // P[g+8][..]
            uint32_t pa2 = cvt_bf16x2(e4, e5);   // P[g][16kc+8+2t4 ..]
            uint32_t pa3 = cvt_bf16x2(e6, e7);   // P[g+8][..]

            // ---- O-mma B fragments from transposed layout ----
            uint32_t q0n0 = *reinterpret_cast<const uint32_t*>(&sHt[g * S_T + 16 * kc + 2 * t4]);
            uint32_t q1n0 = *reinterpret_cast<const uint32_t*>(&sHt[g * S_T + 16 * kc + 2 * t4 + 8]);
            uint32_t q0n1 = *reinterpret_cast<const uint32_t*>(&sHt[(g + 8) * S_T + 16 * kc + 2 * t4]);
            uint32_t q1n1 = *reinterpret_cast<const uint32_t*>(&sHt[(g + 8) * S_T + 16 * kc + 2 * t4 + 8]);

            mma_bf16(o00, o01, o02, o03, pa0, pa1, pa2, pa3, q0n0, q1n0);
            mma_bf16(o10, o11, o12, o13, pa0, pa1, pa2, pa3, q0n1, q1n1);
        }
    }

    // den: reduce across the 4 lanes sharing each row g
    den_g  += __shfl_xor_sync(0xffffffffu, den_g, 1);
    den_g  += __shfl_xor_sync(0xffffffffu, den_g, 2);
    den_g8 += __shfl_xor_sync(0xffffffffu, den_g8, 1);
    den_g8 += __shfl_xor_sync(0xffffffffu, den_g8, 2);

    float* pn  = g_pnum + ((size_t)split * NN + rg) * CLS;
    float* pn8 = g_pnum + ((size_t)split * NN + rg8) * CLS;
    *reinterpret_cast<float2*>(&pn [2 * t4])     = make_float2(o00, o01);
    *reinterpret_cast<float2*>(&pn [2 * t4 + 8]) = make_float2(o10, o11);
    *reinterpret_cast<float2*>(&pn8[2 * t4])     = make_float2(o02, o03);
    *reinterpret_cast<float2*>(&pn8[2 * t4 + 8]) = make_float2(o12, o13);
    if (t4 == 0) {
        g_pden[split * NN + rg]  = den_g;
        g_pden[split * NN + rg8] = den_g8;
    }
}

// ---------------------------------------------------------------------------
// Kernel 3: reduce split partials, out = num/den, then row log-softmax.
// ---------------------------------------------------------------------------
__global__ void finalize_kernel(float* __restrict__ out) {
    const int row = blockIdx.x * blockDim.x + threadIdx.x;
    if (row >= NN) return;

    float acc[CLS];
#pragma unroll
    for (int c = 0; c < CLS; c++) acc[c] = 0.f;
    float den = 0.f;

#pragma unroll
    for (int s = 0; s < NSPLIT; s++) {
        const float4* pn = reinterpret_cast<const float4*>(
            g_pnum + ((size_t)s * NN + row) * CLS);
#pragma unroll
        for (int q = 0; q < 4; q++) {
            float4 v = pn[q];
            acc[q * 4 + 0] += v.x; acc[q * 4 + 1] += v.y;
            acc[q * 4 + 2] += v.z; acc[q * 4 + 3] += v.w;
        }
        den += g_pden[s * NN + row];
    }

    const float inv = 1.0f / den;
    float o[CLS];
    float m = -CUDART_INF_F;
#pragma unroll
    for (int c = 0; c < CLS; c++) { o[c] = acc[c] * inv; m = fmaxf(m, o[c]); }
    float sum = 0.f;
#pragma unroll
    for (int c = 0; c < CLS; c++) sum += expf(o[c] - m);
    const float lse = logf(sum) + m;

    float4* dst = reinterpret_cast<float4*>(out + (size_t)row * CLS);
#pragma unroll
    for (int q = 0; q < 4; q++)
        dst[q] = make_float4(o[q * 4 + 0] - lse, o[q * 4 + 1] - lse,
                             o[q * 4 + 2] - lse, o[q * 4 + 3] - lse);
}

// ---------------------------------------------------------------------------
extern "C" void kernel_launch(void* const* d_in, const int* in_sizes, int n_in,
                              void* d_out, int out_size) {
    const float* x  = (const float*)d_in[0];
    const float* W1 = (const float*)d_in[1];
    const float* b1 = (const float*)d_in[2];
    const float* W2 = (const float*)d_in[3];
    const float* b2 = (const float*)d_in[4];
    const float* W3 = (const float*)d_in[5];
    const float* b3 = (const float*)d_in[6];
    float* out = (float*)d_out;

    mlp_kernel<<<NN / 64, 256>>>(x, W1, b1, W2, b2, W3, b3);

    dim3 grid(NN / ROWS_CTA, NSPLIT);
    agg_kernel<<<grid, 256>>>();

    finalize_kernel<<<NN / 256, 256>>>(out);
}

// round 3
// speedup vs baseline: 3.4641x; 1.3137x over previous
#include <cuda_runtime.h>
#include <cuda_bf16.h>
#include <math_constants.h>
#include <cstdint>

// Problem constants
#define NN   12288
#define DIM  128
#define HID  16
#define CLS  16

// Aggregation tiling
#define NSPLIT   3
#define COLS_PS  (NN / NSPLIT)     // 4096 columns per split
#define CHUNK    256               // columns staged per pass
#define ROWS_CTA 128               // 8 warps x 16 rows

// smem strides (bf16 elements), bank-conflict-free (verified lane maps)
#define S_N 24     // natural layout Hc[j][hid], j-stride
#define S_T 264    // transposed layout HcT[hid][j], hid-stride

#define SQRT_LOG2E 1.2011224087864498f   // sqrt(log2(e))

// Device scratch (no cudaMalloc allowed)
__device__ __align__(16) float g_Wc[DIM * CLS];               // combined weight
__device__ __align__(16) float g_bc[CLS];                     // combined bias
__device__ __align__(16) __nv_bfloat16 g_Hs[NN * HID];        // h * sqrt(log2e), bf16
__device__ __align__(16) __nv_bfloat16 g_Hb[NN * HID];        // h, bf16
__device__ __align__(16) float g_pnum[NSPLIT * NN * CLS];     // partial numerators
__device__ __align__(16) float g_pden[NSPLIT * NN];           // partial denominators

// ---------------------------------------------------------------------------
// PTX helpers
// ---------------------------------------------------------------------------
__device__ __forceinline__ void mma_bf16(float& d0, float& d1, float& d2, float& d3,
                                         uint32_t a0, uint32_t a1, uint32_t a2, uint32_t a3,
                                         uint32_t b0, uint32_t b1) {
    asm volatile(
        "mma.sync.aligned.m16n8k16.row.col.f32.bf16.bf16.f32 "
        "{%0,%1,%2,%3}, {%4,%5,%6,%7}, {%8,%9}, {%0,%1,%2,%3};"
        : "+f"(d0), "+f"(d1), "+f"(d2), "+f"(d3)
        : "r"(a0), "r"(a1), "r"(a2), "r"(a3), "r"(b0), "r"(b1));
}

__device__ __forceinline__ uint32_t cvt_bf16x2(float lo, float hi) {
    uint32_t r;
    asm("cvt.rn.bf16x2.f32 %0, %1, %2;" : "=r"(r) : "f"(hi), "f"(lo));
    return r;
}

__device__ __forceinline__ float ex2f(float x) {
    float r;
    asm("ex2.approx.ftz.f32 %0, %1;" : "=f"(r) : "f"(x));
    return r;
}

// ---------------------------------------------------------------------------
// Kernel 0: combined linear weights (layers are purely linear: no activation).
// Wc = W1 @ W2 @ W3 ; bc = (b1 @ W2 + b2) @ W3 + b3.  One block, 128 threads.
// ---------------------------------------------------------------------------
__global__ void precompute_kernel(const float* __restrict__ W1, const float* __restrict__ b1,
                                  const float* __restrict__ W2, const float* __restrict__ b2,
                                  const float* __restrict__ W3, const float* __restrict__ b3) {
    __shared__ float sW2[HID * HID];
    __shared__ float sW3[HID * CLS];
    const int t = threadIdx.x;
    for (int i = t; i < HID * HID; i += 128) sW2[i] = W2[i];
    for (int i = t; i < HID * CLS; i += 128) sW3[i] = W3[i];
    __syncthreads();

    // thread k computes row k of Wc
    float v[HID];
#pragma unroll
    for (int j = 0; j < HID; j++) v[j] = 0.f;
#pragma unroll
    for (int p = 0; p < HID; p++) {
        const float w = W1[t * HID + p];
#pragma unroll
        for (int j = 0; j < HID; j++) v[j] = fmaf(w, sW2[p * HID + j], v[j]);
    }
    float w[CLS];
#pragma unroll
    for (int j = 0; j < CLS; j++) w[j] = 0.f;
#pragma unroll
    for (int p = 0; p < HID; p++) {
#pragma unroll
        for (int j = 0; j < CLS; j++) w[j] = fmaf(v[p], sW3[p * CLS + j], w[j]);
    }
#pragma unroll
    for (int j = 0; j < CLS; j++) g_Wc[t * CLS + j] = w[j];

    if (t == 0) {
        float u[HID];
#pragma unroll
        for (int j = 0; j < HID; j++) u[j] = b2[j];
#pragma unroll
        for (int p = 0; p < HID; p++)
#pragma unroll
            for (int j = 0; j < HID; j++) u[j] = fmaf(b1[p], sW2[p * HID + j], u[j]);
        float bb[CLS];
#pragma unroll
        for (int j = 0; j < CLS; j++) bb[j] = b3[j];
#pragma unroll
        for (int p = 0; p < HID; p++)
#pragma unroll
            for (int j = 0; j < CLS; j++) bb[j] = fmaf(u[p], sW3[p * CLS + j], bb[j]);
#pragma unroll
        for (int j = 0; j < CLS; j++) g_bc[j] = bb[j];
    }
}

// ---------------------------------------------------------------------------
// Kernel 1: h = x @ Wc + bc -> g_Hs (scaled bf16) and g_Hb (bf16).
// 4 threads per row, strided k (k = sub + 4*kk) -> conflict-free smem reads.
// ---------------------------------------------------------------------------
__global__ __launch_bounds__(256)
void mlp_gemm(const float* __restrict__ x) {
    __shared__ float sWc[DIM * CLS];   // 8 KB
    __shared__ float sbc[CLS];

    const int tid = threadIdx.x;
    {
        const float4* src = reinterpret_cast<const float4*>(g_Wc);
        float4* dst = reinterpret_cast<float4*>(sWc);
#pragma unroll
        for (int i = 0; i < 2; i++) dst[tid + 256 * i] = src[tid + 256 * i];
        if (tid < CLS) sbc[tid] = g_bc[tid];
    }
    __syncthreads();

    const int sub = tid & 3;
    const int row = blockIdx.x * 64 + (tid >> 2);

    float acc[CLS];
#pragma unroll
    for (int j = 0; j < CLS; j++) acc[j] = 0.f;

    const float* xr = x + (size_t)row * DIM;
#pragma unroll
    for (int kk = 0; kk < 32; kk++) {
        const int k = sub + 4 * kk;
        const float xk = __ldg(&xr[k]);
        const float4* wr = reinterpret_cast<const float4*>(&sWc[k * CLS]);
        float4 w0 = wr[0], w1 = wr[1], w2 = wr[2], w3 = wr[3];
        acc[0]  = fmaf(xk, w0.x, acc[0]);  acc[1]  = fmaf(xk, w0.y, acc[1]);
        acc[2]  = fmaf(xk, w0.z, acc[2]);  acc[3]  = fmaf(xk, w0.w, acc[3]);
        acc[4]  = fmaf(xk, w1.x, acc[4]);  acc[5]  = fmaf(xk, w1.y, acc[5]);
        acc[6]  = fmaf(xk, w1.z, acc[6]);  acc[7]  = fmaf(xk, w1.w, acc[7]);
        acc[8]  = fmaf(xk, w2.x, acc[8]);  acc[9]  = fmaf(xk, w2.y, acc[9]);
        acc[10] = fmaf(xk, w2.z, acc[10]); acc[11] = fmaf(xk, w2.w, acc[11]);
        acc[12] = fmaf(xk, w3.x, acc[12]); acc[13] = fmaf(xk, w3.y, acc[13]);
        acc[14] = fmaf(xk, w3.z, acc[14]); acc[15] = fmaf(xk, w3.w, acc[15]);
    }

#pragma unroll
    for (int j = 0; j < CLS; j++) {
        acc[j] += __shfl_xor_sync(0xffffffffu, acc[j], 1);
        acc[j] += __shfl_xor_sync(0xffffffffu, acc[j], 2);
    }

    if (sub == 0) {
        float h[CLS];
#pragma unroll
        for (int j = 0; j < CLS; j++) h[j] = acc[j] + sbc[j];
        uint32_t* du = reinterpret_cast<uint32_t*>(g_Hb + (size_t)row * HID);
        uint32_t* ds = reinterpret_cast<uint32_t*>(g_Hs + (size_t)row * HID);
#pragma unroll
        for (int q = 0; q < 8; q++) {
            du[q] = cvt_bf16x2(h[2 * q], h[2 * q + 1]);
            ds[q] = cvt_bf16x2(h[2 * q] * SQRT_LOG2E, h[2 * q + 1] * SQRT_LOG2E);
        }
    }
}

// ---------------------------------------------------------------------------
// Kernel 2: fused masked-softmax aggregation on tensor cores.
// S' = Hs @ Hs^T = log2e * (h_i . h_j) via bf16 HMMA; e = (s'>0)? 2^s' : 0;
// O += P @ Hb via second HMMA (C-fragment reused as A-fragment).
// ---------------------------------------------------------------------------
__global__ __launch_bounds__(256)
void agg_kernel() {
    __shared__ __align__(16) __nv_bfloat16 sHn[CHUNK * S_N];  // Hs[j][hid] (scaled)
    __shared__ __align__(16) __nv_bfloat16 sHt[HID * S_T];    // Hb^T[hid][j] (unscaled)

    const int tid  = threadIdx.x;
    const int lane = tid & 31;
    const int wid  = tid >> 5;        // 0..7
    const int g    = lane >> 2;       // 0..7
    const int t4   = lane & 3;        // 0..3

    const int split = blockIdx.y;
    const int rbase = blockIdx.x * ROWS_CTA + wid * 16;
    const int rg  = rbase + g;
    const int rg8 = rg + 8;

    // A-fragment: scaled rows (loop-invariant)
    uint32_t a0 = *reinterpret_cast<const uint32_t*>(g_Hs + (size_t)rg  * HID + 2 * t4);
    uint32_t a1 = *reinterpret_cast<const uint32_t*>(g_Hs + (size_t)rg8 * HID + 2 * t4);
    uint32_t a2 = *reinterpret_cast<const uint32_t*>(g_Hs + (size_t)rg  * HID + 2 * t4 + 8);
    uint32_t a3 = *reinterpret_cast<const uint32_t*>(g_Hs + (size_t)rg8 * HID + 2 * t4 + 8);

    float o00 = 0.f, o01 = 0.f, o02 = 0.f, o03 = 0.f;
    float o10 = 0.f, o11 = 0.f, o12 = 0.f, o13 = 0.f;
    float den_g = 0.f, den_g8 = 0.f;

    const int j0 = split * COLS_PS;

    for (int cc = 0; cc < COLS_PS; cc += CHUNK) {
        __syncthreads();
        // Stage: thread `tid` owns column j = tid of this chunk.
        {
            const int j = tid;
            const size_t gidx = (size_t)(j0 + cc + j) * HID;
            const uint4 vs0 = *reinterpret_cast<const uint4*>(g_Hs + gidx);
            const uint4 vs1 = *reinterpret_cast<const uint4*>(g_Hs + gidx + 8);
            *reinterpret_cast<uint4*>(&sHn[j * S_N])     = vs0;
            *reinterpret_cast<uint4*>(&sHn[j * S_N + 8]) = vs1;

            const uint4 vu0 = *reinterpret_cast<const uint4*>(g_Hb + gidx);
            const uint4 vu1 = *reinterpret_cast<const uint4*>(g_Hb + gidx + 8);
            const uint32_t u[8] = {vu0.x, vu0.y, vu0.z, vu0.w, vu1.x, vu1.y, vu1.z, vu1.w};
#pragma unroll
            for (int w = 0; w < 8; w++) {
                __nv_bfloat162 bp = *reinterpret_cast<const __nv_bfloat162*>(&u[w]);
                sHt[(2 * w)     * S_T + j] = bp.x;
                sHt[(2 * w + 1) * S_T + j] = bp.y;
            }
        }
        __syncthreads();

#pragma unroll
        for (int kc = 0; kc < CHUNK / 16; kc++) {
            const int ja = 16 * kc + g;
            const int jb = ja + 8;
            uint32_t b0a = *reinterpret_cast<const uint32_t*>(&sHn[ja * S_N + 2 * t4]);
            uint32_t b1a = *reinterpret_cast<const uint32_t*>(&sHn[ja * S_N + 2 * t4 + 8]);
            uint32_t b0b = *reinterpret_cast<const uint32_t*>(&sHn[jb * S_N + 2 * t4]);
            uint32_t b1b = *reinterpret_cast<const uint32_t*>(&sHn[jb * S_N + 2 * t4 + 8]);

            float s0 = 0.f, s1 = 0.f, s2 = 0.f, s3 = 0.f;
            float s4 = 0.f, s5 = 0.f, s6 = 0.f, s7 = 0.f;
            mma_bf16(s0, s1, s2, s3, a0, a1, a2, a3, b0a, b1a);
            mma_bf16(s4, s5, s6, s7, a0, a1, a2, a3, b0b, b1b);

            // e = (s>0) ? 2^s : 0   (s already scaled by log2e)
            float e0 = ex2f(s0); e0 = (s0 > 0.f) ? e0 : 0.f;
            float e1 = ex2f(s1); e1 = (s1 > 0.f) ? e1 : 0.f;
            float e2 = ex2f(s2); e2 = (s2 > 0.f) ? e2 : 0.f;
            float e3 = ex2f(s3); e3 = (s3 > 0.f) ? e3 : 0.f;
            float e4 = ex2f(s4); e4 = (s4 > 0.f) ? e4 : 0.f;
            float e5 = ex2f(s5); e5 = (s5 > 0.f) ? e5 : 0.f;
            float e6 = ex2f(s6); e6 = (s6 > 0.f) ? e6 : 0.f;
            float e7 = ex2f(s7); e7 = (s7 > 0.f) ? e7 : 0.f;

            den_g  += (e0 + e1) + (e4 + e5);
            den_g8 += (e2 + e3) + (e6 + e7);

            uint32_t pa0 = cvt_bf16x2(e0, e1);
            uint32_t pa1 = cvt_bf16x2(e2, e3);
            uint32_t pa2 = cvt_bf16x2(e4, e5);
            uint32_t pa3 = cvt_bf16x2(e6, e7);

            uint32_t q0n0 = *reinterpret_cast<const uint32_t*>(&sHt[g * S_T + 16 * kc + 2 * t4]);
            uint32_t q1n0 = *reinterpret_cast<const uint32_t*>(&sHt[g * S_T + 16 * kc + 2 * t4 + 8]);
            uint32_t q0n1 = *reinterpret_cast<const uint32_t*>(&sHt[(g + 8) * S_T + 16 * kc + 2 * t4]);
            uint32_t q1n1 = *reinterpret_cast<const uint32_t*>(&sHt[(g + 8) * S_T + 16 * kc + 2 * t4 + 8]);

            mma_bf16(o00, o01, o02, o03, pa0, pa1, pa2, pa3, q0n0, q1n0);
            mma_bf16(o10, o11, o12, o13, pa0, pa1, pa2, pa3, q0n1, q1n1);
        }
    }

    den_g  += __shfl_xor_sync(0xffffffffu, den_g, 1);
    den_g  += __shfl_xor_sync(0xffffffffu, den_g, 2);
    den_g8 += __shfl_xor_sync(0xffffffffu, den_g8, 1);
    den_g8 += __shfl_xor_sync(0xffffffffu, den_g8, 2);

    float* pn  = g_pnum + ((size_t)split * NN + rg) * CLS;
    float* pn8 = g_pnum + ((size_t)split * NN + rg8) * CLS;
    *reinterpret_cast<float2*>(&pn [2 * t4])     = make_float2(o00, o01);
    *reinterpret_cast<float2*>(&pn [2 * t4 + 8]) = make_float2(o10, o11);
    *reinterpret_cast<float2*>(&pn8[2 * t4])     = make_float2(o02, o03);
    *reinterpret_cast<float2*>(&pn8[2 * t4 + 8]) = make_float2(o12, o13);
    if (t4 == 0) {
        g_pden[split * NN + rg]  = den_g;
        g_pden[split * NN + rg8] = den_g8;
    }
}

// ---------------------------------------------------------------------------
// Kernel 3: reduce split partials, out = num/den, then row log-softmax.
// ---------------------------------------------------------------------------
__global__ void finalize_kernel(float* __restrict__ out) {
    const int row = blockIdx.x * blockDim.x + threadIdx.x;
    if (row >= NN) return;

    float acc[CLS];
#pragma unroll
    for (int c = 0; c < CLS; c++) acc[c] = 0.f;
    float den = 0.f;

#pragma unroll
    for (int s = 0; s < NSPLIT; s++) {
        const float4* pn = reinterpret_cast<const float4*>(
            g_pnum + ((size_t)s * NN + row) * CLS);
#pragma unroll
        for (int q = 0; q < 4; q++) {
            float4 v = pn[q];
            acc[q * 4 + 0] += v.x; acc[q * 4 + 1] += v.y;
            acc[q * 4 + 2] += v.z; acc[q * 4 + 3] += v.w;
        }
        den += g_pden[s * NN + row];
    }

    const float inv = 1.0f / den;
    float o[CLS];
    float m = -CUDART_INF_F;
#pragma unroll
    for (int c = 0; c < CLS; c++) { o[c] = acc[c] * inv; m = fmaxf(m, o[c]); }
    float sum = 0.f;
#pragma unroll
    for (int c = 0; c < CLS; c++) sum += expf(o[c] - m);
    const float lse = logf(sum) + m;

    float4* dst = reinterpret_cast<float4*>(out + (size_t)row * CLS);
#pragma unroll
    for (int q = 0; q < 4; q++)
        dst[q] = make_float4(o[q * 4 + 0] - lse, o[q * 4 + 1] - lse,
                             o[q * 4 + 2] - lse, o[q * 4 + 3] - lse);
}

// ---------------------------------------------------------------------------
extern "C" void kernel_launch(void* const* d_in, const int* in_sizes, int n_in,
                              void* d_out, int out_size) {
    const float* x  = (const float*)d_in[0];
    const float* W1 = (const float*)d_in[1];
    const float* b1 = (const float*)d_in[2];
    const float* W2 = (const float*)d_in[3];
    const float* b2 = (const float*)d_in[4];
    const float* W3 = (const float*)d_in[5];
    const float* b3 = (const float*)d_in[6];
    float* out = (float*)d_out;

    precompute_kernel<<<1, 128>>>(W1, b1, W2, b2, W3, b3);
    mlp_gemm<<<NN / 64, 256>>>(x);

    dim3 grid(NN / ROWS_CTA, NSPLIT);
    agg_kernel<<<grid, 256>>>();

    finalize_kernel<<<NN / 256, 256>>>(out);
}

// round 5
// speedup vs baseline: 4.0184x; 1.1600x over previous
#include <cuda_runtime.h>
#include <cuda_bf16.h>
#include <math_constants.h>
#include <cstdint>

// Problem constants
#define NN   12288
#define DIM  128
#define HID  16
#define CLS  16

// Aggregation tiling
#define NSPLIT   6
#define COLS_PS  (NN / NSPLIT)     // 2048 columns per split
#define CHUNK    256               // columns staged per pass
#define ROWS_CTA 128               // 8 warps x 16 rows

// smem strides (bf16 elements), bank-conflict-free (verified lane maps)
#define S_N 24     // natural layout Hc[j][hid], j-stride
#define S_T 264    // transposed layout HcT[hid][j], hid-stride

#define SQRT_LOG2E 1.2011224087864498f   // sqrt(log2(e))

// Device scratch (no cudaMalloc allowed)
__device__ __align__(16) __nv_bfloat16 g_Hs[NN * HID];        // h * sqrt(log2e), bf16
__device__ __align__(16) __nv_bfloat16 g_Hb[NN * HID];        // h, bf16
__device__ __align__(16) float g_pnum[NSPLIT * NN * CLS];     // partial numerators
__device__ __align__(16) float g_pden[NSPLIT * NN];           // partial denominators

// ---------------------------------------------------------------------------
// PTX helpers
// ---------------------------------------------------------------------------
__device__ __forceinline__ void mma_bf16(float& d0, float& d1, float& d2, float& d3,
                                         uint32_t a0, uint32_t a1, uint32_t a2, uint32_t a3,
                                         uint32_t b0, uint32_t b1) {
    asm volatile(
        "mma.sync.aligned.m16n8k16.row.col.f32.bf16.bf16.f32 "
        "{%0,%1,%2,%3}, {%4,%5,%6,%7}, {%8,%9}, {%0,%1,%2,%3};"
        : "+f"(d0), "+f"(d1), "+f"(d2), "+f"(d3)
        : "r"(a0), "r"(a1), "r"(a2), "r"(a3), "r"(b0), "r"(b1));
}

__device__ __forceinline__ uint32_t cvt_bf16x2(float lo, float hi) {
    uint32_t r;
    asm("cvt.rn.bf16x2.f32 %0, %1, %2;" : "=r"(r) : "f"(hi), "f"(lo));
    return r;
}

__device__ __forceinline__ float ex2f(float x) {
    float r;
    asm("ex2.approx.ftz.f32 %0, %1;" : "=f"(r) : "f"(x));
    return r;
}

// ---------------------------------------------------------------------------
// Kernel 1: fused weight-collapse + GEMM.
// The 3 layers are purely linear (no activation is applied in the reference),
// so h = x @ (W1 W2 W3) + ((b1 W2 + b2) W3 + b3). Each CTA rebuilds the tiny
// combined weight in smem, then does the thin GEMM. Emits h (bf16) and
// h*sqrt(log2e) (bf16).
// ---------------------------------------------------------------------------
__global__ __launch_bounds__(256)
void mlp_gemm(const float* __restrict__ x,
              const float* __restrict__ W1, const float* __restrict__ b1,
              const float* __restrict__ W2, const float* __restrict__ b2,
              const float* __restrict__ W3, const float* __restrict__ b3) {
    __shared__ float sW2[HID * HID];
    __shared__ float sW3[HID * CLS];
    __shared__ float sWc[DIM * CLS];   // 8 KB
    __shared__ float sbc[CLS];
    __shared__ float su[HID];

    const int tid = threadIdx.x;
    // NOTE: HID*HID == 256 == blockDim; strided loops load BOTH arrays.
    for (int i = tid; i < HID * HID; i += 256) sW2[i] = W2[i];
    for (int i = tid; i < HID * CLS; i += 256) sW3[i] = W3[i];
    __syncthreads();

    if (tid < DIM) {
        // row tid of Wc = (W1 @ W2 @ W3)[tid]
        float v[HID];
#pragma unroll
        for (int j = 0; j < HID; j++) v[j] = 0.f;
#pragma unroll
        for (int p = 0; p < HID; p++) {
            const float w = __ldg(&W1[tid * HID + p]);
#pragma unroll
            for (int j = 0; j < HID; j++) v[j] = fmaf(w, sW2[p * HID + j], v[j]);
        }
        float w[CLS];
#pragma unroll
        for (int j = 0; j < CLS; j++) w[j] = 0.f;
#pragma unroll
        for (int p = 0; p < HID; p++)
#pragma unroll
            for (int j = 0; j < CLS; j++) w[j] = fmaf(v[p], sW3[p * CLS + j], w[j]);
#pragma unroll
        for (int j = 0; j < CLS; j++) sWc[tid * CLS + j] = w[j];
    } else if (tid < DIM + HID) {
        // u[p] = (b1 @ W2 + b2)[p]
        const int p = tid - DIM;
        float u = __ldg(&b2[p]);
#pragma unroll
        for (int k = 0; k < HID; k++) u = fmaf(__ldg(&b1[k]), sW2[k * HID + p], u);
        su[p] = u;
    }
    __syncthreads();

    if (tid < CLS) {
        float bb = __ldg(&b3[tid]);
#pragma unroll
        for (int p = 0; p < HID; p++) bb = fmaf(su[p], sW3[p * CLS + tid], bb);
        sbc[tid] = bb;
    }
    __syncthreads();

    const int sub = tid & 3;
    const int row = blockIdx.x * 64 + (tid >> 2);

    float acc[CLS];
#pragma unroll
    for (int j = 0; j < CLS; j++) acc[j] = 0.f;

    const float* xr = x + (size_t)row * DIM;
#pragma unroll
    for (int kk = 0; kk < 32; kk++) {
        const int k = sub + 4 * kk;
        const float xk = __ldg(&xr[k]);
        const float4* wr = reinterpret_cast<const float4*>(&sWc[k * CLS]);
        float4 w0 = wr[0], w1 = wr[1], w2 = wr[2], w3 = wr[3];
        acc[0]  = fmaf(xk, w0.x, acc[0]);  acc[1]  = fmaf(xk, w0.y, acc[1]);
        acc[2]  = fmaf(xk, w0.z, acc[2]);  acc[3]  = fmaf(xk, w0.w, acc[3]);
        acc[4]  = fmaf(xk, w1.x, acc[4]);  acc[5]  = fmaf(xk, w1.y, acc[5]);
        acc[6]  = fmaf(xk, w1.z, acc[6]);  acc[7]  = fmaf(xk, w1.w, acc[7]);
        acc[8]  = fmaf(xk, w2.x, acc[8]);  acc[9]  = fmaf(xk, w2.y, acc[9]);
        acc[10] = fmaf(xk, w2.z, acc[10]); acc[11] = fmaf(xk, w2.w, acc[11]);
        acc[12] = fmaf(xk, w3.x, acc[12]); acc[13] = fmaf(xk, w3.y, acc[13]);
        acc[14] = fmaf(xk, w3.z, acc[14]); acc[15] = fmaf(xk, w3.w, acc[15]);
    }

#pragma unroll
    for (int j = 0; j < CLS; j++) {
        acc[j] += __shfl_xor_sync(0xffffffffu, acc[j], 1);
        acc[j] += __shfl_xor_sync(0xffffffffu, acc[j], 2);
    }

    if (sub == 0) {
        float h[CLS];
#pragma unroll
        for (int j = 0; j < CLS; j++) h[j] = acc[j] + sbc[j];
        uint32_t* du = reinterpret_cast<uint32_t*>(g_Hb + (size_t)row * HID);
        uint32_t* ds = reinterpret_cast<uint32_t*>(g_Hs + (size_t)row * HID);
#pragma unroll
        for (int q = 0; q < 8; q++) {
            du[q] = cvt_bf16x2(h[2 * q], h[2 * q + 1]);
            ds[q] = cvt_bf16x2(h[2 * q] * SQRT_LOG2E, h[2 * q + 1] * SQRT_LOG2E);
        }
    }
}

// ---------------------------------------------------------------------------
// Kernel 2: fused masked-softmax aggregation on tensor cores.
// S' = Hs @ Hs^T = log2e * (h_i . h_j) via bf16 HMMA; e = (s'>0)? 2^s' : 0;
// O += P @ Hb via second HMMA (C-fragment reused as A-fragment).
// ---------------------------------------------------------------------------
__global__ __launch_bounds__(256, 3)
void agg_kernel() {
    __shared__ __align__(16) __nv_bfloat16 sHn[CHUNK * S_N];  // Hs[j][hid] (scaled)
    __shared__ __align__(16) __nv_bfloat16 sHt[HID * S_T];    // Hb^T[hid][j] (unscaled)

    const int tid  = threadIdx.x;
    const int lane = tid & 31;
    const int wid  = tid >> 5;        // 0..7
    const int g    = lane >> 2;       // 0..7
    const int t4   = lane & 3;        // 0..3

    const int split = blockIdx.y;
    const int rbase = blockIdx.x * ROWS_CTA + wid * 16;
    const int rg  = rbase + g;
    const int rg8 = rg + 8;

    // A-fragment: scaled rows (loop-invariant)
    uint32_t a0 = *reinterpret_cast<const uint32_t*>(g_Hs + (size_t)rg  * HID + 2 * t4);
    uint32_t a1 = *reinterpret_cast<const uint32_t*>(g_Hs + (size_t)rg8 * HID + 2 * t4);
    uint32_t a2 = *reinterpret_cast<const uint32_t*>(g_Hs + (size_t)rg  * HID + 2 * t4 + 8);
    uint32_t a3 = *reinterpret_cast<const uint32_t*>(g_Hs + (size_t)rg8 * HID + 2 * t4 + 8);

    float o00 = 0.f, o01 = 0.f, o02 = 0.f, o03 = 0.f;
    float o10 = 0.f, o11 = 0.f, o12 = 0.f, o13 = 0.f;
    float den_g = 0.f, den_g8 = 0.f;

    const int j0 = split * COLS_PS;

    for (int cc = 0; cc < COLS_PS; cc += CHUNK) {
        __syncthreads();
        // Stage: thread `tid` owns column j = tid of this chunk.
        {
            const int j = tid;
            const size_t gidx = (size_t)(j0 + cc + j) * HID;
            const uint4 vs0 = *reinterpret_cast<const uint4*>(g_Hs + gidx);
            const uint4 vs1 = *reinterpret_cast<const uint4*>(g_Hs + gidx + 8);
            *reinterpret_cast<uint4*>(&sHn[j * S_N])     = vs0;
            *reinterpret_cast<uint4*>(&sHn[j * S_N + 8]) = vs1;

            const uint4 vu0 = *reinterpret_cast<const uint4*>(g_Hb + gidx);
            const uint4 vu1 = *reinterpret_cast<const uint4*>(g_Hb + gidx + 8);
            const uint32_t u[8] = {vu0.x, vu0.y, vu0.z, vu0.w, vu1.x, vu1.y, vu1.z, vu1.w};
#pragma unroll
            for (int w = 0; w < 8; w++) {
                __nv_bfloat162 bp = *reinterpret_cast<const __nv_bfloat162*>(&u[w]);
                sHt[(2 * w)     * S_T + j] = bp.x;
                sHt[(2 * w + 1) * S_T + j] = bp.y;
            }
        }
        __syncthreads();

#pragma unroll
        for (int kc = 0; kc < CHUNK / 16; kc++) {
            const int ja = 16 * kc + g;
            const int jb = ja + 8;
            uint32_t b0a = *reinterpret_cast<const uint32_t*>(&sHn[ja * S_N + 2 * t4]);
            uint32_t b1a = *reinterpret_cast<const uint32_t*>(&sHn[ja * S_N + 2 * t4 + 8]);
            uint32_t b0b = *reinterpret_cast<const uint32_t*>(&sHn[jb * S_N + 2 * t4]);
            uint32_t b1b = *reinterpret_cast<const uint32_t*>(&sHn[jb * S_N + 2 * t4 + 8]);

            float s0 = 0.f, s1 = 0.f, s2 = 0.f, s3 = 0.f;
            float s4 = 0.f, s5 = 0.f, s6 = 0.f, s7 = 0.f;
            mma_bf16(s0, s1, s2, s3, a0, a1, a2, a3, b0a, b1a);
            mma_bf16(s4, s5, s6, s7, a0, a1, a2, a3, b0b, b1b);

            // e = (s>0) ? 2^s : 0   (s already scaled by log2e)
            float e0 = ex2f(s0); e0 = (s0 > 0.f) ? e0 : 0.f;
            float e1 = ex2f(s1); e1 = (s1 > 0.f) ? e1 : 0.f;
            float e2 = ex2f(s2); e2 = (s2 > 0.f) ? e2 : 0.f;
            float e3 = ex2f(s3); e3 = (s3 > 0.f) ? e3 : 0.f;
            float e4 = ex2f(s4); e4 = (s4 > 0.f) ? e4 : 0.f;
            float e5 = ex2f(s5); e5 = (s5 > 0.f) ? e5 : 0.f;
            float e6 = ex2f(s6); e6 = (s6 > 0.f) ? e6 : 0.f;
            float e7 = ex2f(s7); e7 = (s7 > 0.f) ? e7 : 0.f;

            den_g  += (e0 + e1) + (e4 + e5);
            den_g8 += (e2 + e3) + (e6 + e7);

            uint32_t pa0 = cvt_bf16x2(e0, e1);
            uint32_t pa1 = cvt_bf16x2(e2, e3);
            uint32_t pa2 = cvt_bf16x2(e4, e5);
            uint32_t pa3 = cvt_bf16x2(e6, e7);

            uint32_t q0n0 = *reinterpret_cast<const uint32_t*>(&sHt[g * S_T + 16 * kc + 2 * t4]);
            uint32_t q1n0 = *reinterpret_cast<const uint32_t*>(&sHt[g * S_T + 16 * kc + 2 * t4 + 8]);
            uint32_t q0n1 = *reinterpret_cast<const uint32_t*>(&sHt[(g + 8) * S_T + 16 * kc + 2 * t4]);
            uint32_t q1n1 = *reinterpret_cast<const uint32_t*>(&sHt[(g + 8) * S_T + 16 * kc + 2 * t4 + 8]);

            mma_bf16(o00, o01, o02, o03, pa0, pa1, pa2, pa3, q0n0, q1n0);
            mma_bf16(o10, o11, o12, o13, pa0, pa1, pa2, pa3, q0n1, q1n1);
        }
    }

    den_g  += __shfl_xor_sync(0xffffffffu, den_g, 1);
    den_g  += __shfl_xor_sync(0xffffffffu, den_g, 2);
    den_g8 += __shfl_xor_sync(0xffffffffu, den_g8, 1);
    den_g8 += __shfl_xor_sync(0xffffffffu, den_g8, 2);

    float* pn  = g_pnum + ((size_t)split * NN + rg) * CLS;
    float* pn8 = g_pnum + ((size_t)split * NN + rg8) * CLS;
    *reinterpret_cast<float2*>(&pn [2 * t4])     = make_float2(o00, o01);
    *reinterpret_cast<float2*>(&pn [2 * t4 + 8]) = make_float2(o10, o11);
    *reinterpret_cast<float2*>(&pn8[2 * t4])     = make_float2(o02, o03);
    *reinterpret_cast<float2*>(&pn8[2 * t4 + 8]) = make_float2(o12, o13);
    if (t4 == 0) {
        g_pden[split * NN + rg]  = den_g;
        g_pden[split * NN + rg8] = den_g8;
    }
}

// ---------------------------------------------------------------------------
// Kernel 3: reduce split partials, out = num/den, then row log-softmax.
// 4 threads per row; each owns 4 classes; quad shuffle-reduce for max/lse.
// ---------------------------------------------------------------------------
__global__ __launch_bounds__(256)
void finalize_kernel(float* __restrict__ out) {
    const int idx = blockIdx.x * 256 + threadIdx.x;
    const int row = idx >> 2;
    const int q   = idx & 3;

    float4 acc = make_float4(0.f, 0.f, 0.f, 0.f);
    float den = 0.f;
#pragma unroll
    for (int s = 0; s < NSPLIT; s++) {
        float4 v = *reinterpret_cast<const float4*>(
            g_pnum + ((size_t)s * NN + row) * CLS + 4 * q);
        acc.x += v.x; acc.y += v.y; acc.z += v.z; acc.w += v.w;
        den += g_pden[s * NN + row];
    }

    const float inv = 1.0f / den;
    float o0 = acc.x * inv, o1 = acc.y * inv, o2 = acc.z * inv, o3 = acc.w * inv;

    float m = fmaxf(fmaxf(o0, o1), fmaxf(o2, o3));
    m = fmaxf(m, __shfl_xor_sync(0xffffffffu, m, 1));
    m = fmaxf(m, __shfl_xor_sync(0xffffffffu, m, 2));

    float sum = expf(o0 - m) + expf(o1 - m) + expf(o2 - m) + expf(o3 - m);
    sum += __shfl_xor_sync(0xffffffffu, sum, 1);
    sum += __shfl_xor_sync(0xffffffffu, sum, 2);

    const float lse = logf(sum) + m;
    *reinterpret_cast<float4*>(out + (size_t)row * CLS + 4 * q) =
        make_float4(o0 - lse, o1 - lse, o2 - lse, o3 - lse);
}

// ---------------------------------------------------------------------------
extern "C" void kernel_launch(void* const* d_in, const int* in_sizes, int n_in,
                              void* d_out, int out_size) {
    const float* x  = (const float*)d_in[0];
    const float* W1 = (const float*)d_in[1];
    const float* b1 = (const float*)d_in[2];
    const float* W2 = (const float*)d_in[3];
    const float* b2 = (const float*)d_in[4];
    const float* W3 = (const float*)d_in[5];
    const float* b3 = (const float*)d_in[6];
    float* out = (float*)d_out;

    mlp_gemm<<<NN / 64, 256>>>(x, W1, b1, W2, b2, W3, b3);

    dim3 grid(NN / ROWS_CTA, NSPLIT);
    agg_kernel<<<grid, 256>>>();

    finalize_kernel<<<(NN * 4) / 256, 256>>>(out);
}

// round 6
// speedup vs baseline: 4.1487x; 1.0324x over previous
#include <cuda_runtime.h>
#include <cuda_bf16.h>
#include <math_constants.h>
#include <cstdint>

// Problem constants
#define NN   12288
#define DIM  128
#define HID  16
#define CLS  16

// Aggregation tiling
#define NSPLIT   6
#define COLS_PS  (NN / NSPLIT)     // 2048 columns per split
#define CHUNK    256               // columns staged per pass
#define ROWS_CTA 128               // 8 warps x 16 rows

// smem strides (bf16 elements), bank-conflict-free (verified lane maps)
#define S_N 24     // natural layout Hc[j][hid], j-stride
#define S_T 264    // transposed layout HcT[hid][j], hid-stride

#define SQRT_LOG2E 1.2011224087864498f   // sqrt(log2(e))

// Device scratch (no cudaMalloc allowed)
__device__ __align__(16) float g_Wc[DIM * CLS];               // combined weight
__device__ __align__(16) float g_bc[CLS];                     // combined bias
__device__ __align__(16) __nv_bfloat16 g_Hs[NN * HID];        // h * sqrt(log2e), bf16
__device__ __align__(16) __nv_bfloat16 g_Hb[NN * HID];        // h, bf16
__device__ __align__(16) float g_pnum[NSPLIT * NN * CLS];     // partial numerators
__device__ __align__(16) float g_pden[NSPLIT * NN];           // partial denominators

// ---------------------------------------------------------------------------
// PTX helpers
// ---------------------------------------------------------------------------
__device__ __forceinline__ void mma_bf16(float& d0, float& d1, float& d2, float& d3,
                                         uint32_t a0, uint32_t a1, uint32_t a2, uint32_t a3,
                                         uint32_t b0, uint32_t b1) {
    asm volatile(
        "mma.sync.aligned.m16n8k16.row.col.f32.bf16.bf16.f32 "
        "{%0,%1,%2,%3}, {%4,%5,%6,%7}, {%8,%9}, {%0,%1,%2,%3};"
        : "+f"(d0), "+f"(d1), "+f"(d2), "+f"(d3)
        : "r"(a0), "r"(a1), "r"(a2), "r"(a3), "r"(b0), "r"(b1));
}

__device__ __forceinline__ uint32_t cvt_bf16x2(float lo, float hi) {
    uint32_t r;
    asm("cvt.rn.bf16x2.f32 %0, %1, %2;" : "=r"(r) : "f"(hi), "f"(lo));
    return r;
}

__device__ __forceinline__ float ex2f(float x) {
    float r;
    asm("ex2.approx.ftz.f32 %0, %1;" : "=f"(r) : "f"(x));
    return r;
}

// ---------------------------------------------------------------------------
// Kernel 0: combined linear weights (layers are purely linear: no activation).
// Wc = W1 @ W2 @ W3 ; bc = (b1 @ W2 + b2) @ W3 + b3.  One block, 128 threads.
// ---------------------------------------------------------------------------
__global__ void precompute_kernel(const float* __restrict__ W1, const float* __restrict__ b1,
                                  const float* __restrict__ W2, const float* __restrict__ b2,
                                  const float* __restrict__ W3, const float* __restrict__ b3) {
    __shared__ float sW2[HID * HID];
    __shared__ float sW3[HID * CLS];
    const int t = threadIdx.x;
    for (int i = t; i < HID * HID; i += 128) sW2[i] = W2[i];
    for (int i = t; i < HID * CLS; i += 128) sW3[i] = W3[i];
    __syncthreads();

    // thread k computes row k of Wc
    float v[HID];
#pragma unroll
    for (int j = 0; j < HID; j++) v[j] = 0.f;
#pragma unroll
    for (int p = 0; p < HID; p++) {
        const float w = W1[t * HID + p];
#pragma unroll
        for (int j = 0; j < HID; j++) v[j] = fmaf(w, sW2[p * HID + j], v[j]);
    }
    float w[CLS];
#pragma unroll
    for (int j = 0; j < CLS; j++) w[j] = 0.f;
#pragma unroll
    for (int p = 0; p < HID; p++) {
#pragma unroll
        for (int j = 0; j < CLS; j++) w[j] = fmaf(v[p], sW3[p * CLS + j], w[j]);
    }
#pragma unroll
    for (int j = 0; j < CLS; j++) g_Wc[t * CLS + j] = w[j];

    if (t == 0) {
        float u[HID];
#pragma unroll
        for (int j = 0; j < HID; j++) u[j] = b2[j];
#pragma unroll
        for (int p = 0; p < HID; p++)
#pragma unroll
            for (int j = 0; j < HID; j++) u[j] = fmaf(b1[p], sW2[p * HID + j], u[j]);
        float bb[CLS];
#pragma unroll
        for (int j = 0; j < CLS; j++) bb[j] = b3[j];
#pragma unroll
        for (int p = 0; p < HID; p++)
#pragma unroll
            for (int j = 0; j < CLS; j++) bb[j] = fmaf(u[p], sW3[p * CLS + j], bb[j]);
#pragma unroll
        for (int j = 0; j < CLS; j++) g_bc[j] = bb[j];
    }
}

// ---------------------------------------------------------------------------
// Kernel 1: h = x @ Wc + bc -> g_Hs (scaled bf16) and g_Hb (bf16).
// One thread per (row, class): 768 CTAs x 256 threads for high occupancy.
// x loads dedup across the 16 j-lanes sharing a row; Wc reads are scalar LDS
// with consecutive-j lanes -> conflict-free (row duplicates broadcast).
// ---------------------------------------------------------------------------
__global__ __launch_bounds__(256)
void mlp_gemm(const float* __restrict__ x) {
    __shared__ float sWc[DIM * CLS];   // 8 KB
    __shared__ float sbc[CLS];

    const int tid = threadIdx.x;
    {
        const float4* src = reinterpret_cast<const float4*>(g_Wc);
        float4* dst = reinterpret_cast<float4*>(sWc);
        dst[tid]       = src[tid];
        dst[tid + 256] = src[tid + 256];
        if (tid < CLS) sbc[tid] = g_bc[tid];
    }
    __syncthreads();

    const int row = blockIdx.x * 16 + (tid >> 4);
    const int j   = tid & 15;

    const float4* xr = reinterpret_cast<const float4*>(x + (size_t)row * DIM);
    float a0 = 0.f, a1 = 0.f, a2 = 0.f, a3 = 0.f;
#pragma unroll
    for (int k4 = 0; k4 < 32; k4++) {
        const float4 xv = __ldg(&xr[k4]);
        a0 = fmaf(xv.x, sWc[(4 * k4 + 0) * CLS + j], a0);
        a1 = fmaf(xv.y, sWc[(4 * k4 + 1) * CLS + j], a1);
        a2 = fmaf(xv.z, sWc[(4 * k4 + 2) * CLS + j], a2);
        a3 = fmaf(xv.w, sWc[(4 * k4 + 3) * CLS + j], a3);
    }
    const float h = (a0 + a1) + (a2 + a3) + sbc[j];

    g_Hb[(size_t)row * HID + j] = __float2bfloat16(h);
    g_Hs[(size_t)row * HID + j] = __float2bfloat16(h * SQRT_LOG2E);
}

// ---------------------------------------------------------------------------
// Kernel 2: fused masked-softmax aggregation on tensor cores.
// S' = Hs @ Hs^T = log2e * (h_i . h_j) via bf16 HMMA; e = (s'>0)? 2^s' : 0;
// O += P @ Hb via second HMMA (C-fragment reused as A-fragment).
// ---------------------------------------------------------------------------
__global__ __launch_bounds__(256, 3)
void agg_kernel() {
    __shared__ __align__(16) __nv_bfloat16 sHn[CHUNK * S_N];  // Hs[j][hid] (scaled)
    __shared__ __align__(16) __nv_bfloat16 sHt[HID * S_T];    // Hb^T[hid][j] (unscaled)

    const int tid  = threadIdx.x;
    const int lane = tid & 31;
    const int wid  = tid >> 5;        // 0..7
    const int g    = lane >> 2;       // 0..7
    const int t4   = lane & 3;        // 0..3

    const int split = blockIdx.y;
    const int rbase = blockIdx.x * ROWS_CTA + wid * 16;
    const int rg  = rbase + g;
    const int rg8 = rg + 8;

    // A-fragment: scaled rows (loop-invariant)
    uint32_t a0 = *reinterpret_cast<const uint32_t*>(g_Hs + (size_t)rg  * HID + 2 * t4);
    uint32_t a1 = *reinterpret_cast<const uint32_t*>(g_Hs + (size_t)rg8 * HID + 2 * t4);
    uint32_t a2 = *reinterpret_cast<const uint32_t*>(g_Hs + (size_t)rg  * HID + 2 * t4 + 8);
    uint32_t a3 = *reinterpret_cast<const uint32_t*>(g_Hs + (size_t)rg8 * HID + 2 * t4 + 8);

    float o00 = 0.f, o01 = 0.f, o02 = 0.f, o03 = 0.f;
    float o10 = 0.f, o11 = 0.f, o12 = 0.f, o13 = 0.f;
    float den_g = 0.f, den_g8 = 0.f;

    const int j0 = split * COLS_PS;

    for (int cc = 0; cc < COLS_PS; cc += CHUNK) {
        __syncthreads();
        // Stage: thread `tid` owns column j = tid of this chunk.
        {
            const int j = tid;
            const size_t gidx = (size_t)(j0 + cc + j) * HID;
            const uint4 vs0 = *reinterpret_cast<const uint4*>(g_Hs + gidx);
            const uint4 vs1 = *reinterpret_cast<const uint4*>(g_Hs + gidx + 8);
            *reinterpret_cast<uint4*>(&sHn[j * S_N])     = vs0;
            *reinterpret_cast<uint4*>(&sHn[j * S_N + 8]) = vs1;

            const uint4 vu0 = *reinterpret_cast<const uint4*>(g_Hb + gidx);
            const uint4 vu1 = *reinterpret_cast<const uint4*>(g_Hb + gidx + 8);
            const uint32_t u[8] = {vu0.x, vu0.y, vu0.z, vu0.w, vu1.x, vu1.y, vu1.z, vu1.w};
#pragma unroll
            for (int w = 0; w < 8; w++) {
                __nv_bfloat162 bp = *reinterpret_cast<const __nv_bfloat162*>(&u[w]);
                sHt[(2 * w)     * S_T + j] = bp.x;
                sHt[(2 * w + 1) * S_T + j] = bp.y;
            }
        }
        __syncthreads();

#pragma unroll
        for (int kc = 0; kc < CHUNK / 16; kc++) {
            const int ja = 16 * kc + g;
            const int jb = ja + 8;
            uint32_t b0a = *reinterpret_cast<const uint32_t*>(&sHn[ja * S_N + 2 * t4]);
            uint32_t b1a = *reinterpret_cast<const uint32_t*>(&sHn[ja * S_N + 2 * t4 + 8]);
            uint32_t b0b = *reinterpret_cast<const uint32_t*>(&sHn[jb * S_N + 2 * t4]);
            uint32_t b1b = *reinterpret_cast<const uint32_t*>(&sHn[jb * S_N + 2 * t4 + 8]);

            float s0 = 0.f, s1 = 0.f, s2 = 0.f, s3 = 0.f;
            float s4 = 0.f, s5 = 0.f, s6 = 0.f, s7 = 0.f;
            mma_bf16(s0, s1, s2, s3, a0, a1, a2, a3, b0a, b1a);
            mma_bf16(s4, s5, s6, s7, a0, a1, a2, a3, b0b, b1b);

            // e = (s>0) ? 2^s : 0   (s already scaled by log2e)
            float e0 = ex2f(s0); e0 = (s0 > 0.f) ? e0 : 0.f;
            float e1 = ex2f(s1); e1 = (s1 > 0.f) ? e1 : 0.f;
            float e2 = ex2f(s2); e2 = (s2 > 0.f) ? e2 : 0.f;
            float e3 = ex2f(s3); e3 = (s3 > 0.f) ? e3 : 0.f;
            float e4 = ex2f(s4); e4 = (s4 > 0.f) ? e4 : 0.f;
            float e5 = ex2f(s5); e5 = (s5 > 0.f) ? e5 : 0.f;
            float e6 = ex2f(s6); e6 = (s6 > 0.f) ? e6 : 0.f;
            float e7 = ex2f(s7); e7 = (s7 > 0.f) ? e7 : 0.f;

            den_g  += (e0 + e1) + (e4 + e5);
            den_g8 += (e2 + e3) + (e6 + e7);

            uint32_t pa0 = cvt_bf16x2(e0, e1);
            uint32_t pa1 = cvt_bf16x2(e2, e3);
            uint32_t pa2 = cvt_bf16x2(e4, e5);
            uint32_t pa3 = cvt_bf16x2(e6, e7);

            uint32_t q0n0 = *reinterpret_cast<const uint32_t*>(&sHt[g * S_T + 16 * kc + 2 * t4]);
            uint32_t q1n0 = *reinterpret_cast<const uint32_t*>(&sHt[g * S_T + 16 * kc + 2 * t4 + 8]);
            uint32_t q0n1 = *reinterpret_cast<const uint32_t*>(&sHt[(g + 8) * S_T + 16 * kc + 2 * t4]);
            uint32_t q1n1 = *reinterpret_cast<const uint32_t*>(&sHt[(g + 8) * S_T + 16 * kc + 2 * t4 + 8]);

            mma_bf16(o00, o01, o02, o03, pa0, pa1, pa2, pa3, q0n0, q1n0);
            mma_bf16(o10, o11, o12, o13, pa0, pa1, pa2, pa3, q0n1, q1n1);
        }
    }

    den_g  += __shfl_xor_sync(0xffffffffu, den_g, 1);
    den_g  += __shfl_xor_sync(0xffffffffu, den_g, 2);
    den_g8 += __shfl_xor_sync(0xffffffffu, den_g8, 1);
    den_g8 += __shfl_xor_sync(0xffffffffu, den_g8, 2);

    float* pn  = g_pnum + ((size_t)split * NN + rg) * CLS;
    float* pn8 = g_pnum + ((size_t)split * NN + rg8) * CLS;
    *reinterpret_cast<float2*>(&pn [2 * t4])     = make_float2(o00, o01);
    *reinterpret_cast<float2*>(&pn [2 * t4 + 8]) = make_float2(o10, o11);
    *reinterpret_cast<float2*>(&pn8[2 * t4])     = make_float2(o02, o03);
    *reinterpret_cast<float2*>(&pn8[2 * t4 + 8]) = make_float2(o12, o13);
    if (t4 == 0) {
        g_pden[split * NN + rg]  = den_g;
        g_pden[split * NN + rg8] = den_g8;
    }
}

// ---------------------------------------------------------------------------
// Kernel 3: reduce split partials, out = num/den, then row log-softmax.
// 4 threads per row; each owns 4 classes; quad shuffle-reduce for max/lse.
// ---------------------------------------------------------------------------
__global__ __launch_bounds__(256)
void finalize_kernel(float* __restrict__ out) {
    const int idx = blockIdx.x * 256 + threadIdx.x;
    const int row = idx >> 2;
    const int q   = idx & 3;

    float4 acc = make_float4(0.f, 0.f, 0.f, 0.f);
    float den = 0.f;
#pragma unroll
    for (int s = 0; s < NSPLIT; s++) {
        float4 v = *reinterpret_cast<const float4*>(
            g_pnum + ((size_t)s * NN + row) * CLS + 4 * q);
        acc.x += v.x; acc.y += v.y; acc.z += v.z; acc.w += v.w;
        den += g_pden[s * NN + row];
    }

    const float inv = 1.0f / den;
    float o0 = acc.x * inv, o1 = acc.y * inv, o2 = acc.z * inv, o3 = acc.w * inv;

    float m = fmaxf(fmaxf(o0, o1), fmaxf(o2, o3));
    m = fmaxf(m, __shfl_xor_sync(0xffffffffu, m, 1));
    m = fmaxf(m, __shfl_xor_sync(0xffffffffu, m, 2));

    float sum = expf(o0 - m) + expf(o1 - m) + expf(o2 - m) + expf(o3 - m);
    sum += __shfl_xor_sync(0xffffffffu, sum, 1);
    sum += __shfl_xor_sync(0xffffffffu, sum, 2);

    const float lse = logf(sum) + m;
    *reinterpret_cast<float4*>(out + (size_t)row * CLS + 4 * q) =
        make_float4(o0 - lse, o1 - lse, o2 - lse, o3 - lse);
}

// ---------------------------------------------------------------------------
extern "C" void kernel_launch(void* const* d_in, const int* in_sizes, int n_in,
                              void* d_out, int out_size) {
    const float* x  = (const float*)d_in[0];
    const float* W1 = (const float*)d_in[1];
    const float* b1 = (const float*)d_in[2];
    const float* W2 = (const float*)d_in[3];
    const float* b2 = (const float*)d_in[4];
    const float* W3 = (const float*)d_in[5];
    const float* b3 = (const float*)d_in[6];
    float* out = (float*)d_out;

    precompute_kernel<<<1, 128>>>(W1, b1, W2, b2, W3, b3);
    mlp_gemm<<<NN / 16, 256>>>(x);

    dim3 grid(NN / ROWS_CTA, NSPLIT);
    agg_kernel<<<grid, 256>>>();

    finalize_kernel<<<(NN * 4) / 256, 256>>>(out);
}

// round 7
// speedup vs baseline: 4.4585x; 1.0747x over previous
#include <cuda_runtime.h>
#include <cuda_bf16.h>
#include <math_constants.h>
#include <cstdint>

// Problem constants
#define NN   12288
#define DIM  128
#define HID  16
#define CLS  16

// Aggregation tiling
#define NSPLIT   6
#define COLS_PS  (NN / NSPLIT)     // 2048 columns per split
#define CHUNK    256               // columns staged per pass
#define ROWS_CTA 128               // 8 warps x 16 rows

// smem strides (bf16 elements), bank-conflict-free (verified lane maps)
#define S_N 24     // natural layout Hs[j][hid], j-stride
#define S_T 264    // transposed layout HsT[hid][j], hid-stride

#define SQRT_LOG2E 1.2011224087864498f   // sqrt(log2(e))

// Device scratch (no cudaMalloc allowed)
__device__ __align__(16) float g_Wc[DIM * CLS];               // combined weight
__device__ __align__(16) float g_bc[CLS];                     // combined bias
__device__ __align__(16) __nv_bfloat16 g_Hs[NN * HID];        // h * sqrt(log2e), bf16
__device__ __align__(16) float g_pnum[NSPLIT * NN * CLS];     // partial numerators (scaled)
__device__ __align__(16) float g_pden[NSPLIT * NN];           // partial denominators

// ---------------------------------------------------------------------------
// PTX helpers
// ---------------------------------------------------------------------------
__device__ __forceinline__ void mma_bf16(float& d0, float& d1, float& d2, float& d3,
                                         uint32_t a0, uint32_t a1, uint32_t a2, uint32_t a3,
                                         uint32_t b0, uint32_t b1) {
    asm volatile(
        "mma.sync.aligned.m16n8k16.row.col.f32.bf16.bf16.f32 "
        "{%0,%1,%2,%3}, {%4,%5,%6,%7}, {%8,%9}, {%0,%1,%2,%3};"
        : "+f"(d0), "+f"(d1), "+f"(d2), "+f"(d3)
        : "r"(a0), "r"(a1), "r"(a2), "r"(a3), "r"(b0), "r"(b1));
}

// packs {lo, hi} -> bf16x2 register (lo in low 16 bits)
__device__ __forceinline__ uint32_t cvt_bf16x2(float lo, float hi) {
    uint32_t r;
    asm("cvt.rn.bf16x2.f32 %0, %1, %2;" : "=r"(r) : "f"(hi), "f"(lo));
    return r;
}

// packed 2^x on bf16x2 (one MUFU pass)
__device__ __forceinline__ uint32_t ex2_bf16x2(uint32_t x) {
    uint32_t r;
    asm("ex2.approx.ftz.bf16x2 %0, %1;" : "=r"(r) : "r"(x));
    return r;
}

__device__ __forceinline__ uint32_t b2u(__nv_bfloat162 v) {
    return *reinterpret_cast<uint32_t*>(&v);
}
__device__ __forceinline__ __nv_bfloat162 u2b(uint32_t v) {
    return *reinterpret_cast<__nv_bfloat162*>(&v);
}

// masked exp on a packed pair: e = (s > 0) ? 2^s : 0
__device__ __forceinline__ uint32_t masked_exp2(uint32_t ps, __nv_bfloat162 z2) {
    uint32_t pe = ex2_bf16x2(ps);
    __nv_bfloat162 m = __hgt2(u2b(ps), z2);   // 1.0 / 0.0 per half
    return b2u(__hmul2(u2b(pe), m));
}

// ---------------------------------------------------------------------------
// Kernel 0: combined linear weights (layers are purely linear: no activation).
// Wc = W1 @ W2 @ W3 ; bc = (b1 @ W2 + b2) @ W3 + b3.  One block, 128 threads.
// ---------------------------------------------------------------------------
__global__ void precompute_kernel(const float* __restrict__ W1, const float* __restrict__ b1,
                                  const float* __restrict__ W2, const float* __restrict__ b2,
                                  const float* __restrict__ W3, const float* __restrict__ b3) {
    __shared__ float sW2[HID * HID];
    __shared__ float sW3[HID * CLS];
    const int t = threadIdx.x;
    for (int i = t; i < HID * HID; i += 128) sW2[i] = W2[i];
    for (int i = t; i < HID * CLS; i += 128) sW3[i] = W3[i];
    __syncthreads();

    // thread k computes row k of Wc
    float v[HID];
#pragma unroll
    for (int j = 0; j < HID; j++) v[j] = 0.f;
#pragma unroll
    for (int p = 0; p < HID; p++) {
        const float w = W1[t * HID + p];
#pragma unroll
        for (int j = 0; j < HID; j++) v[j] = fmaf(w, sW2[p * HID + j], v[j]);
    }
    float w[CLS];
#pragma unroll
    for (int j = 0; j < CLS; j++) w[j] = 0.f;
#pragma unroll
    for (int p = 0; p < HID; p++) {
#pragma unroll
        for (int j = 0; j < CLS; j++) w[j] = fmaf(v[p], sW3[p * CLS + j], w[j]);
    }
#pragma unroll
    for (int j = 0; j < CLS; j++) g_Wc[t * CLS + j] = w[j];

    if (t == 0) {
        float u[HID];
#pragma unroll
        for (int j = 0; j < HID; j++) u[j] = b2[j];
#pragma unroll
        for (int p = 0; p < HID; p++)
#pragma unroll
            for (int j = 0; j < HID; j++) u[j] = fmaf(b1[p], sW2[p * HID + j], u[j]);
        float bb[CLS];
#pragma unroll
        for (int j = 0; j < CLS; j++) bb[j] = b3[j];
#pragma unroll
        for (int p = 0; p < HID; p++)
#pragma unroll
            for (int j = 0; j < CLS; j++) bb[j] = fmaf(u[p], sW3[p * CLS + j], bb[j]);
#pragma unroll
        for (int j = 0; j < CLS; j++) g_bc[j] = bb[j];
    }
}

// ---------------------------------------------------------------------------
// Kernel 1: h = x @ Wc + bc -> g_Hs = bf16(h * sqrt(log2e)).
// One thread per (row, class): 768 CTAs x 256 threads for high occupancy.
// ---------------------------------------------------------------------------
__global__ __launch_bounds__(256)
void mlp_gemm(const float* __restrict__ x) {
    __shared__ float sWc[DIM * CLS];   // 8 KB
    __shared__ float sbc[CLS];

    const int tid = threadIdx.x;
    {
        const float4* src = reinterpret_cast<const float4*>(g_Wc);
        float4* dst = reinterpret_cast<float4*>(sWc);
        dst[tid]       = src[tid];
        dst[tid + 256] = src[tid + 256];
        if (tid < CLS) sbc[tid] = g_bc[tid];
    }
    __syncthreads();

    const int row = blockIdx.x * 16 + (tid >> 4);
    const int j   = tid & 15;

    const float4* xr = reinterpret_cast<const float4*>(x + (size_t)row * DIM);
    float a0 = 0.f, a1 = 0.f, a2 = 0.f, a3 = 0.f;
#pragma unroll
    for (int k4 = 0; k4 < 32; k4++) {
        const float4 xv = __ldg(&xr[k4]);
        a0 = fmaf(xv.x, sWc[(4 * k4 + 0) * CLS + j], a0);
        a1 = fmaf(xv.y, sWc[(4 * k4 + 1) * CLS + j], a1);
        a2 = fmaf(xv.z, sWc[(4 * k4 + 2) * CLS + j], a2);
        a3 = fmaf(xv.w, sWc[(4 * k4 + 3) * CLS + j], a3);
    }
    const float h = (a0 + a1) + (a2 + a3) + sbc[j];

    g_Hs[(size_t)row * HID + j] = __float2bfloat16(h * SQRT_LOG2E);
}

// ---------------------------------------------------------------------------
// Kernel 2: fused masked-softmax aggregation on tensor cores.
// S' = Hs @ Hs^T = log2e * (h_i . h_j) via bf16 HMMA;
// e  = (s'>0) ? 2^s' : 0 via PACKED bf16x2 ex2 + packed mask;
// O' += P @ Hs (scaled by sqrt(log2e), corrected in finalize);
// den via a 3rd HMMA against a constant ones-column B-fragment.
// ---------------------------------------------------------------------------
__global__ __launch_bounds__(256, 3)
void agg_kernel() {
    __shared__ __align__(16) __nv_bfloat16 sHn[CHUNK * S_N];  // Hs[j][hid]
    __shared__ __align__(16) __nv_bfloat16 sHt[HID * S_T];    // Hs^T[hid][j]

    const int tid  = threadIdx.x;
    const int lane = tid & 31;
    const int wid  = tid >> 5;        // 0..7
    const int g    = lane >> 2;       // 0..7
    const int t4   = lane & 3;        // 0..3

    const int split = blockIdx.y;
    const int rbase = blockIdx.x * ROWS_CTA + wid * 16;
    const int rg  = rbase + g;
    const int rg8 = rg + 8;

    // A-fragment: scaled rows (loop-invariant)
    uint32_t a0 = *reinterpret_cast<const uint32_t*>(g_Hs + (size_t)rg  * HID + 2 * t4);
    uint32_t a1 = *reinterpret_cast<const uint32_t*>(g_Hs + (size_t)rg8 * HID + 2 * t4);
    uint32_t a2 = *reinterpret_cast<const uint32_t*>(g_Hs + (size_t)rg  * HID + 2 * t4 + 8);
    uint32_t a3 = *reinterpret_cast<const uint32_t*>(g_Hs + (size_t)rg8 * HID + 2 * t4 + 8);

    // den B-fragment: ones in column n=0 only -> lanes with g==0 hold {1,1}
    const uint32_t bden = (g == 0) ? 0x3F803F80u : 0u;
    const __nv_bfloat162 z2 = u2b(0u);

    float o00 = 0.f, o01 = 0.f, o02 = 0.f, o03 = 0.f;
    float o10 = 0.f, o11 = 0.f, o12 = 0.f, o13 = 0.f;
    float dd0 = 0.f, dd1 = 0.f, dd2 = 0.f, dd3 = 0.f;   // den at n=0 (t4==0 lanes)

    const int j0 = split * COLS_PS;

    for (int cc = 0; cc < COLS_PS; cc += CHUNK) {
        __syncthreads();
        // Stage: thread `tid` owns column j = tid of this chunk (single source array).
        {
            const int j = tid;
            const size_t gidx = (size_t)(j0 + cc + j) * HID;
            const uint4 vs0 = *reinterpret_cast<const uint4*>(g_Hs + gidx);
            const uint4 vs1 = *reinterpret_cast<const uint4*>(g_Hs + gidx + 8);
            *reinterpret_cast<uint4*>(&sHn[j * S_N])     = vs0;
            *reinterpret_cast<uint4*>(&sHn[j * S_N + 8]) = vs1;

            const uint32_t u[8] = {vs0.x, vs0.y, vs0.z, vs0.w, vs1.x, vs1.y, vs1.z, vs1.w};
#pragma unroll
            for (int w = 0; w < 8; w++) {
                __nv_bfloat162 bp = u2b(u[w]);
                sHt[(2 * w)     * S_T + j] = bp.x;
                sHt[(2 * w + 1) * S_T + j] = bp.y;
            }
        }
        __syncthreads();

#pragma unroll
        for (int kc = 0; kc < CHUNK / 16; kc++) {
            const int ja = 16 * kc + g;
            const int jb = ja + 8;
            uint32_t b0a = *reinterpret_cast<const uint32_t*>(&sHn[ja * S_N + 2 * t4]);
            uint32_t b1a = *reinterpret_cast<const uint32_t*>(&sHn[ja * S_N + 2 * t4 + 8]);
            uint32_t b0b = *reinterpret_cast<const uint32_t*>(&sHn[jb * S_N + 2 * t4]);
            uint32_t b1b = *reinterpret_cast<const uint32_t*>(&sHn[jb * S_N + 2 * t4 + 8]);

            float s0 = 0.f, s1 = 0.f, s2 = 0.f, s3 = 0.f;
            float s4 = 0.f, s5 = 0.f, s6 = 0.f, s7 = 0.f;
            mma_bf16(s0, s1, s2, s3, a0, a1, a2, a3, b0a, b1a);
            mma_bf16(s4, s5, s6, s7, a0, a1, a2, a3, b0b, b1b);

            // pack s -> bf16x2, then packed masked exp
            uint32_t pa0 = masked_exp2(cvt_bf16x2(s0, s1), z2);   // P[g   ][2t4..]
            uint32_t pa1 = masked_exp2(cvt_bf16x2(s2, s3), z2);   // P[g+8 ][2t4..]
            uint32_t pa2 = masked_exp2(cvt_bf16x2(s4, s5), z2);   // P[g   ][8+2t4..]
            uint32_t pa3 = masked_exp2(cvt_bf16x2(s6, s7), z2);   // P[g+8 ][8+2t4..]

            uint32_t q0n0 = *reinterpret_cast<const uint32_t*>(&sHt[g * S_T + 16 * kc + 2 * t4]);
            uint32_t q1n0 = *reinterpret_cast<const uint32_t*>(&sHt[g * S_T + 16 * kc + 2 * t4 + 8]);
            uint32_t q0n1 = *reinterpret_cast<const uint32_t*>(&sHt[(g + 8) * S_T + 16 * kc + 2 * t4]);
            uint32_t q1n1 = *reinterpret_cast<const uint32_t*>(&sHt[(g + 8) * S_T + 16 * kc + 2 * t4 + 8]);

            mma_bf16(o00, o01, o02, o03, pa0, pa1, pa2, pa3, q0n0, q1n0);
            mma_bf16(o10, o11, o12, o13, pa0, pa1, pa2, pa3, q0n1, q1n1);
            mma_bf16(dd0, dd1, dd2, dd3, pa0, pa1, pa2, pa3, bden, bden);
        }
    }

    float* pn  = g_pnum + ((size_t)split * NN + rg) * CLS;
    float* pn8 = g_pnum + ((size_t)split * NN + rg8) * CLS;
    *reinterpret_cast<float2*>(&pn [2 * t4])     = make_float2(o00, o01);
    *reinterpret_cast<float2*>(&pn [2 * t4 + 8]) = make_float2(o10, o11);
    *reinterpret_cast<float2*>(&pn8[2 * t4])     = make_float2(o02, o03);
    *reinterpret_cast<float2*>(&pn8[2 * t4 + 8]) = make_float2(o12, o13);
    if (t4 == 0) {
        g_pden[split * NN + rg]  = dd0;   // D[g][0]
        g_pden[split * NN + rg8] = dd2;   // D[g+8][0]
    }
}

// ---------------------------------------------------------------------------
// Kernel 3: reduce split partials, out = num/(den*sqrt(log2e)), row log-softmax.
// 4 threads per row; each owns 4 classes; quad shuffle-reduce for max/lse.
// ---------------------------------------------------------------------------
__global__ __launch_bounds__(256)
void finalize_kernel(float* __restrict__ out) {
    const int idx = blockIdx.x * 256 + threadIdx.x;
    const int row = idx >> 2;
    const int q   = idx & 3;

    float4 acc = make_float4(0.f, 0.f, 0.f, 0.f);
    float den = 0.f;
#pragma unroll
    for (int s = 0; s < NSPLIT; s++) {
        float4 v = *reinterpret_cast<const float4*>(
            g_pnum + ((size_t)s * NN + row) * CLS + 4 * q);
        acc.x += v.x; acc.y += v.y; acc.z += v.z; acc.w += v.w;
        den += g_pden[s * NN + row];
    }

    // num is scaled by sqrt(log2e) (O-mma used scaled Hs); correct here.
    const float inv = 1.0f / (den * SQRT_LOG2E);
    float o0 = acc.x * inv, o1 = acc.y * inv, o2 = acc.z * inv, o3 = acc.w * inv;

    float m = fmaxf(fmaxf(o0, o1), fmaxf(o2, o3));
    m = fmaxf(m, __shfl_xor_sync(0xffffffffu, m, 1));
    m = fmaxf(m, __shfl_xor_sync(0xffffffffu, m, 2));

    float sum = expf(o0 - m) + expf(o1 - m) + expf(o2 - m) + expf(o3 - m);
    sum += __shfl_xor_sync(0xffffffffu, sum, 1);
    sum += __shfl_xor_sync(0xffffffffu, sum, 2);

    const float lse = logf(sum) + m;
    *reinterpret_cast<float4*>(out + (size_t)row * CLS + 4 * q) =
        make_float4(o0 - lse, o1 - lse, o2 - lse, o3 - lse);
}

// ---------------------------------------------------------------------------
extern "C" void kernel_launch(void* const* d_in, const int* in_sizes, int n_in,
                              void* d_out, int out_size) {
    const float* x  = (const float*)d_in[0];
    const float* W1 = (const float*)d_in[1];
    const float* b1 = (const float*)d_in[2];
    const float* W2 = (const float*)d_in[3];
    const float* b2 = (const float*)d_in[4];
    const float* W3 = (const float*)d_in[5];
    const float* b3 = (const float*)d_in[6];
    float* out = (float*)d_out;

    precompute_kernel<<<1, 128>>>(W1, b1, W2, b2, W3, b3);
    mlp_gemm<<<NN / 16, 256>>>(x);

    dim3 grid(NN / ROWS_CTA, NSPLIT);
    agg_kernel<<<grid, 256>>>();

    finalize_kernel<<<(NN * 4) / 256, 256>>>(out);
}

// round 8
// speedup vs baseline: 4.4610x; 1.0006x over previous
#include <cuda_runtime.h>
#include <cuda_fp16.h>
#include <math_constants.h>
#include <cstdint>

// Problem constants
#define NN   12288
#define DIM  128
#define HID  16
#define CLS  16

// Aggregation tiling
#define NSPLIT   12
#define COLS_PS  (NN / NSPLIT)     // 1024 columns per split
#define CHUNK    256               // columns staged per pass
#define ROWS_CTA 128               // 8 warps x 16 rows

// smem strides (fp16 elements), bank-conflict-free (verified lane maps)
#define S_N 24     // natural layout Hs[j][hid], j-stride
#define S_T 264    // transposed layout HsT[hid][j], hid-stride

#define SQRT_LOG2E 1.2011224087864498f   // sqrt(log2(e))

// Device scratch (no cudaMalloc allowed)
__device__ __align__(16) float g_Wc[DIM * CLS];               // combined weight
__device__ __align__(16) float g_bc[CLS];                     // combined bias
__device__ __align__(16) __half g_Hs[NN * HID];               // h * sqrt(log2e), fp16
__device__ __align__(16) float g_pnum[NSPLIT * NN * CLS];     // partial numerators (scaled)
__device__ __align__(16) float g_pden[NSPLIT * NN];           // partial denominators

// ---------------------------------------------------------------------------
// PTX helpers
// ---------------------------------------------------------------------------
__device__ __forceinline__ void mma_f16(float& d0, float& d1, float& d2, float& d3,
                                        uint32_t a0, uint32_t a1, uint32_t a2, uint32_t a3,
                                        uint32_t b0, uint32_t b1) {
    asm volatile(
        "mma.sync.aligned.m16n8k16.row.col.f32.f16.f16.f32 "
        "{%0,%1,%2,%3}, {%4,%5,%6,%7}, {%8,%9}, {%0,%1,%2,%3};"
        : "+f"(d0), "+f"(d1), "+f"(d2), "+f"(d3)
        : "r"(a0), "r"(a1), "r"(a2), "r"(a3), "r"(b0), "r"(b1));
}

// packs {lo, hi} -> f16x2 register (lo in low 16 bits)
__device__ __forceinline__ uint32_t cvt_f16x2(float lo, float hi) {
    uint32_t r;
    asm("cvt.rn.f16x2.f32 %0, %1, %2;" : "=r"(r) : "f"(hi), "f"(lo));
    return r;
}

// masked exp on a packed fp16 pair: e = (s > 0) ? 2^s : 0
__device__ __forceinline__ uint32_t masked_exp2h(uint32_t ps) {
    uint32_t pe;
    asm("ex2.approx.f16x2 %0, %1;" : "=r"(pe) : "r"(ps));
    const __half2 z2 = __half2(__ushort_as_half(0), __ushort_as_half(0));
    __half2 m = __hgt2(*reinterpret_cast<__half2*>(&ps), z2);   // 1.0 / 0.0 per half
    __half2 r = __hmul2(*reinterpret_cast<__half2*>(&pe), m);
    return *reinterpret_cast<uint32_t*>(&r);
}

// ---------------------------------------------------------------------------
// Kernel 0: combined linear weights (layers are purely linear: no activation).
// Wc = W1 @ W2 @ W3 ; bc = (b1 @ W2 + b2) @ W3 + b3.  One block, 128 threads.
// ---------------------------------------------------------------------------
__global__ void precompute_kernel(const float* __restrict__ W1, const float* __restrict__ b1,
                                  const float* __restrict__ W2, const float* __restrict__ b2,
                                  const float* __restrict__ W3, const float* __restrict__ b3) {
    __shared__ float sW2[HID * HID];
    __shared__ float sW3[HID * CLS];
    const int t = threadIdx.x;
    for (int i = t; i < HID * HID; i += 128) sW2[i] = W2[i];
    for (int i = t; i < HID * CLS; i += 128) sW3[i] = W3[i];
    __syncthreads();

    // thread k computes row k of Wc
    float v[HID];
#pragma unroll
    for (int j = 0; j < HID; j++) v[j] = 0.f;
#pragma unroll
    for (int p = 0; p < HID; p++) {
        const float w = W1[t * HID + p];
#pragma unroll
        for (int j = 0; j < HID; j++) v[j] = fmaf(w, sW2[p * HID + j], v[j]);
    }
    float w[CLS];
#pragma unroll
    for (int j = 0; j < CLS; j++) w[j] = 0.f;
#pragma unroll
    for (int p = 0; p < HID; p++) {
#pragma unroll
        for (int j = 0; j < CLS; j++) w[j] = fmaf(v[p], sW3[p * CLS + j], w[j]);
    }
#pragma unroll
    for (int j = 0; j < CLS; j++) g_Wc[t * CLS + j] = w[j];

    if (t == 0) {
        float u[HID];
#pragma unroll
        for (int j = 0; j < HID; j++) u[j] = b2[j];
#pragma unroll
        for (int p = 0; p < HID; p++)
#pragma unroll
            for (int j = 0; j < HID; j++) u[j] = fmaf(b1[p], sW2[p * HID + j], u[j]);
        float bb[CLS];
#pragma unroll
        for (int j = 0; j < CLS; j++) bb[j] = b3[j];
#pragma unroll
        for (int p = 0; p < HID; p++)
#pragma unroll
            for (int j = 0; j < CLS; j++) bb[j] = fmaf(u[p], sW3[p * CLS + j], bb[j]);
#pragma unroll
        for (int j = 0; j < CLS; j++) g_bc[j] = bb[j];
    }
}

// ---------------------------------------------------------------------------
// Kernel 1: h = x @ Wc + bc -> g_Hs = fp16(h * sqrt(log2e)).
// One thread per (row, class): 768 CTAs x 256 threads for high occupancy.
// ---------------------------------------------------------------------------
__global__ __launch_bounds__(256)
void mlp_gemm(const float* __restrict__ x) {
    __shared__ float sWc[DIM * CLS];   // 8 KB
    __shared__ float sbc[CLS];

    const int tid = threadIdx.x;
    {
        const float4* src = reinterpret_cast<const float4*>(g_Wc);
        float4* dst = reinterpret_cast<float4*>(sWc);
        dst[tid]       = src[tid];
        dst[tid + 256] = src[tid + 256];
        if (tid < CLS) sbc[tid] = g_bc[tid];
    }
    __syncthreads();

    const int row = blockIdx.x * 16 + (tid >> 4);
    const int j   = tid & 15;

    const float4* xr = reinterpret_cast<const float4*>(x + (size_t)row * DIM);
    float a0 = 0.f, a1 = 0.f, a2 = 0.f, a3 = 0.f;
#pragma unroll
    for (int k4 = 0; k4 < 32; k4++) {
        const float4 xv = __ldg(&xr[k4]);
        a0 = fmaf(xv.x, sWc[(4 * k4 + 0) * CLS + j], a0);
        a1 = fmaf(xv.y, sWc[(4 * k4 + 1) * CLS + j], a1);
        a2 = fmaf(xv.z, sWc[(4 * k4 + 2) * CLS + j], a2);
        a3 = fmaf(xv.w, sWc[(4 * k4 + 3) * CLS + j], a3);
    }
    const float h = (a0 + a1) + (a2 + a3) + sbc[j];

    g_Hs[(size_t)row * HID + j] = __float2half(h * SQRT_LOG2E);
}

// ---------------------------------------------------------------------------
// Kernel 2: fused masked-softmax aggregation on tensor cores (fp16).
// S' = Hs @ Hs^T = log2e * (h_i . h_j) via f16 HMMA (fp32 accum);
// e  = (s'>0) ? 2^s' : 0 via packed f16x2 ex2 + packed mask;
// O' += P @ Hs (scaled by sqrt(log2e), corrected in finalize);
// den via a 3rd HMMA against a constant ones-column B-fragment.
// ---------------------------------------------------------------------------
__global__ __launch_bounds__(256, 3)
void agg_kernel() {
    __shared__ __align__(16) __half sHn[CHUNK * S_N];  // Hs[j][hid]
    __shared__ __align__(16) __half sHt[HID * S_T];    // Hs^T[hid][j]

    const int tid  = threadIdx.x;
    const int lane = tid & 31;
    const int wid  = tid >> 5;        // 0..7
    const int g    = lane >> 2;       // 0..7
    const int t4   = lane & 3;        // 0..3

    const int split = blockIdx.y;
    const int rbase = blockIdx.x * ROWS_CTA + wid * 16;
    const int rg  = rbase + g;
    const int rg8 = rg + 8;

    // A-fragment: scaled rows (loop-invariant)
    uint32_t a0 = *reinterpret_cast<const uint32_t*>(g_Hs + (size_t)rg  * HID + 2 * t4);
    uint32_t a1 = *reinterpret_cast<const uint32_t*>(g_Hs + (size_t)rg8 * HID + 2 * t4);
    uint32_t a2 = *reinterpret_cast<const uint32_t*>(g_Hs + (size_t)rg  * HID + 2 * t4 + 8);
    uint32_t a3 = *reinterpret_cast<const uint32_t*>(g_Hs + (size_t)rg8 * HID + 2 * t4 + 8);

    // den B-fragment: ones in column n=0 only -> lanes with g==0 hold {1,1} fp16
    const uint32_t bden = (g == 0) ? 0x3C003C00u : 0u;

    float o00 = 0.f, o01 = 0.f, o02 = 0.f, o03 = 0.f;
    float o10 = 0.f, o11 = 0.f, o12 = 0.f, o13 = 0.f;
    float dd0 = 0.f, dd1 = 0.f, dd2 = 0.f, dd3 = 0.f;   // den at n=0 (t4==0 lanes)

    const int j0 = split * COLS_PS;

    for (int cc = 0; cc < COLS_PS; cc += CHUNK) {
        __syncthreads();
        // Stage: thread `tid` owns column j = tid of this chunk.
        {
            const int j = tid;
            const size_t gidx = (size_t)(j0 + cc + j) * HID;
            const uint4 vs0 = *reinterpret_cast<const uint4*>(g_Hs + gidx);
            const uint4 vs1 = *reinterpret_cast<const uint4*>(g_Hs + gidx + 8);
            *reinterpret_cast<uint4*>(&sHn[j * S_N])     = vs0;
            *reinterpret_cast<uint4*>(&sHn[j * S_N + 8]) = vs1;

            const uint32_t u[8] = {vs0.x, vs0.y, vs0.z, vs0.w, vs1.x, vs1.y, vs1.z, vs1.w};
#pragma unroll
            for (int w = 0; w < 8; w++) {
                __half2 bp = *reinterpret_cast<const __half2*>(&u[w]);
                sHt[(2 * w)     * S_T + j] = bp.x;
                sHt[(2 * w + 1) * S_T + j] = bp.y;
            }
        }
        __syncthreads();

#pragma unroll
        for (int kc = 0; kc < CHUNK / 16; kc++) {
            const int ja = 16 * kc + g;
            const int jb = ja + 8;
            uint32_t b0a = *reinterpret_cast<const uint32_t*>(&sHn[ja * S_N + 2 * t4]);
            uint32_t b1a = *reinterpret_cast<const uint32_t*>(&sHn[ja * S_N + 2 * t4 + 8]);
            uint32_t b0b = *reinterpret_cast<const uint32_t*>(&sHn[jb * S_N + 2 * t4]);
            uint32_t b1b = *reinterpret_cast<const uint32_t*>(&sHn[jb * S_N + 2 * t4 + 8]);

            float s0 = 0.f, s1 = 0.f, s2 = 0.f, s3 = 0.f;
            float s4 = 0.f, s5 = 0.f, s6 = 0.f, s7 = 0.f;
            mma_f16(s0, s1, s2, s3, a0, a1, a2, a3, b0a, b1a);
            mma_f16(s4, s5, s6, s7, a0, a1, a2, a3, b0b, b1b);

            // pack s -> f16x2, then packed masked exp (target: single dual MUFU)
            uint32_t pa0 = masked_exp2h(cvt_f16x2(s0, s1));   // P[g   ][2t4..]
            uint32_t pa1 = masked_exp2h(cvt_f16x2(s2, s3));   // P[g+8 ][2t4..]
            uint32_t pa2 = masked_exp2h(cvt_f16x2(s4, s5));   // P[g   ][8+2t4..]
            uint32_t pa3 = masked_exp2h(cvt_f16x2(s6, s7));   // P[g+8 ][8+2t4..]

            uint32_t q0n0 = *reinterpret_cast<const uint32_t*>(&sHt[g * S_T + 16 * kc + 2 * t4]);
            uint32_t q1n0 = *reinterpret_cast<const uint32_t*>(&sHt[g * S_T + 16 * kc + 2 * t4 + 8]);
            uint32_t q0n1 = *reinterpret_cast<const uint32_t*>(&sHt[(g + 8) * S_T + 16 * kc + 2 * t4]);
            uint32_t q1n1 = *reinterpret_cast<const uint32_t*>(&sHt[(g + 8) * S_T + 16 * kc + 2 * t4 + 8]);

            mma_f16(o00, o01, o02, o03, pa0, pa1, pa2, pa3, q0n0, q1n0);
            mma_f16(o10, o11, o12, o13, pa0, pa1, pa2, pa3, q0n1, q1n1);
            mma_f16(dd0, dd1, dd2, dd3, pa0, pa1, pa2, pa3, bden, bden);
        }
    }

    float* pn  = g_pnum + ((size_t)split * NN + rg) * CLS;
    float* pn8 = g_pnum + ((size_t)split * NN + rg8) * CLS;
    *reinterpret_cast<float2*>(&pn [2 * t4])     = make_float2(o00, o01);
    *reinterpret_cast<float2*>(&pn [2 * t4 + 8]) = make_float2(o10, o11);
    *reinterpret_cast<float2*>(&pn8[2 * t4])     = make_float2(o02, o03);
    *reinterpret_cast<float2*>(&pn8[2 * t4 + 8]) = make_float2(o12, o13);
    if (t4 == 0) {
        g_pden[split * NN + rg]  = dd0;   // D[g][0]
        g_pden[split * NN + rg8] = dd2;   // D[g+8][0]
    }
}

// ---------------------------------------------------------------------------
// Kernel 3: reduce split partials, out = num/(den*sqrt(log2e)), row log-softmax.
// 8 threads per row; each owns 2 classes; 8-lane shuffle-reduce for max/lse.
// ---------------------------------------------------------------------------
__global__ __launch_bounds__(256)
void finalize_kernel(float* __restrict__ out) {
    const int idx = blockIdx.x * 256 + threadIdx.x;
    const int row = idx >> 3;
    const int p   = idx & 7;

    float n0 = 0.f, n1 = 0.f, den = 0.f;
#pragma unroll
    for (int s = 0; s < NSPLIT; s++) {
        float2 v = *reinterpret_cast<const float2*>(
            g_pnum + ((size_t)s * NN + row) * CLS + 2 * p);
        n0 += v.x; n1 += v.y;
        den += g_pden[s * NN + row];
    }

    // num is scaled by sqrt(log2e) (O-mma used scaled Hs); correct here.
    const float inv = 1.0f / (den * SQRT_LOG2E);
    float o0 = n0 * inv, o1 = n1 * inv;

    float m = fmaxf(o0, o1);
    m = fmaxf(m, __shfl_xor_sync(0xffffffffu, m, 1));
    m = fmaxf(m, __shfl_xor_sync(0xffffffffu, m, 2));
    m = fmaxf(m, __shfl_xor_sync(0xffffffffu, m, 4));

    float sum = expf(o0 - m) + expf(o1 - m);
    sum += __shfl_xor_sync(0xffffffffu, sum, 1);
    sum += __shfl_xor_sync(0xffffffffu, sum, 2);
    sum += __shfl_xor_sync(0xffffffffu, sum, 4);

    const float lse = logf(sum) + m;
    *reinterpret_cast<float2*>(out + (size_t)row * CLS + 2 * p) =
        make_float2(o0 - lse, o1 - lse);
}

// ---------------------------------------------------------------------------
extern "C" void kernel_launch(void* const* d_in, const int* in_sizes, int n_in,
                              void* d_out, int out_size) {
    const float* x  = (const float*)d_in[0];
    const float* W1 = (const float*)d_in[1];
    const float* b1 = (const float*)d_in[2];
    const float* W2 = (const float*)d_in[3];
    const float* b2 = (const float*)d_in[4];
    const float* W3 = (const float*)d_in[5];
    const float* b3 = (const float*)d_in[6];
    float* out = (float*)d_out;

    precompute_kernel<<<1, 128>>>(W1, b1, W2, b2, W3, b3);
    mlp_gemm<<<NN / 16, 256>>>(x);

    dim3 grid(NN / ROWS_CTA, NSPLIT);
    agg_kernel<<<grid, 256>>>();

    finalize_kernel<<<(NN * 8) / 256, 256>>>(out);
}